// round 12
// baseline (speedup 1.0000x reference)
#include <cuda_runtime.h>
#include <cuda_bf16.h>
#include <math.h>
#include <stdint.h>

#define BATCH 64
#define SEQ 256
#define EMB 256
#define NHEAD 8
#define HEADD 32
#define MROWS (BATCH*SEQ)   /* 16384 */
#define ADIM 32
#define NSLOT 42
#define SLOT_SZ 65536

// ---------------- scratch (device globals; no allocation allowed) ------------
__device__ float g_x[MROWS*EMB];
__device__ float g_g[MROWS*EMB];     // swish(gate), fp32
__device__ float g_t[MROWS*EMB];
__device__ float g_z[MROWS*EMB];
__device__ __nv_bfloat16 g_xH[MROWS*EMB], g_xL[MROWS*EMB];
__device__ __nv_bfloat16 g_oH[MROWS*EMB], g_oL[MROWS*EMB];
__device__ __nv_bfloat16 g_zH[MROWS*EMB], g_zL[MROWS*EMB];
__device__ __nv_bfloat16 g_qH[MROWS*EMB], g_qL[MROWS*EMB];
__device__ __nv_bfloat16 g_kH[MROWS*EMB], g_kL[MROWS*EMB];
__device__ __nv_bfloat16 g_vH[MROWS*EMB], g_vL[MROWS*EMB];
__device__ __nv_bfloat16 g_aH[MROWS*ADIM], g_aL[MROWS*ADIM];
__device__ __nv_bfloat16 g_wH[NSLOT*SLOT_SZ], g_wL[NSLOT*SLOT_SZ];

__device__ __forceinline__ float gelu_tanh(float x){
    float x3 = x*x*x;
    return 0.5f*x*(1.f + tanhf(0.7978845608028654f*(x + 0.044715f*x3)));
}
__device__ __forceinline__ float swish_f(float x){
    return x / (1.f + expf(-x));
}
__device__ __forceinline__ uint32_t smem_u32(const void* p){
    uint32_t a;
    asm("{ .reg .u64 t; cvta.to.shared.u64 t, %1; cvt.u32.u64 %0, t; }" : "=r"(a) : "l"(p));
    return a;
}
__device__ __forceinline__ uint32_t pack2(float a, float b, uint32_t& lo){
    __nv_bfloat16 ha = __float2bfloat16(a), hb = __float2bfloat16(b);
    __nv_bfloat16 la = __float2bfloat16(a - __bfloat162float(ha));
    __nv_bfloat16 lb = __float2bfloat16(b - __bfloat162float(hb));
    lo = (uint32_t)__bfloat16_as_ushort(la) | ((uint32_t)__bfloat16_as_ushort(lb)<<16);
    return (uint32_t)__bfloat16_as_ushort(ha) | ((uint32_t)__bfloat16_as_ushort(hb)<<16);
}

#define LDSM4(r, addr) \
    asm volatile("ldmatrix.sync.aligned.m8n8.x4.shared.b16 {%0,%1,%2,%3}, [%4];" \
        : "=r"((r)[0]),"=r"((r)[1]),"=r"((r)[2]),"=r"((r)[3]) : "r"(addr))
#define LDSM2(r, addr) \
    asm volatile("ldmatrix.sync.aligned.m8n8.x2.shared.b16 {%0,%1}, [%2];" \
        : "=r"((r)[0]),"=r"((r)[1]) : "r"(addr))
#define LDSM2T(r, addr) \
    asm volatile("ldmatrix.sync.aligned.m8n8.x2.trans.shared.b16 {%0,%1}, [%2];" \
        : "=r"((r)[0]),"=r"((r)[1]) : "r"(addr))
#define MMA16816(c, a, b) \
    asm volatile("mma.sync.aligned.m16n8k16.row.col.f32.bf16.bf16.f32 " \
        "{%0,%1,%2,%3}, {%4,%5,%6,%7}, {%8,%9}, {%0,%1,%2,%3};" \
        : "+f"((c)[0]),"+f"((c)[1]),"+f"((c)[2]),"+f"((c)[3]) \
        : "r"((a)[0]),"r"((a)[1]),"r"((a)[2]),"r"((a)[3]), "r"((b)[0]),"r"((b)[1]))
#define CPA16(dst, src) \
    asm volatile("cp.async.cg.shared.global [%0],[%1],16;" :: "r"(dst),"l"(src))
#define CPA16Z(dst, src, sz) \
    asm volatile("cp.async.cg.shared.global [%0],[%1],16,%2;" :: "r"(dst),"l"(src),"r"(sz))
#define CPA_COMMIT() asm volatile("cp.async.commit_group;" ::: "memory")
#define CPA_WAIT1()  asm volatile("cp.async.wait_group 1;" ::: "memory")
#define CPA_WAIT0()  asm volatile("cp.async.wait_group 0;" ::: "memory")

// ---------------- conversion kernels -----------------------------------------
struct ConvW { const float* src[NSLOT]; int sz[NSLOT]; };
__global__ void conv_w(ConvW cw, __nv_bfloat16* wh, __nv_bfloat16* wl){
    const int slot = blockIdx.x;
    const int n = cw.sz[slot];
    const float* s = cw.src[slot];
    for (int i = blockIdx.y*blockDim.x + threadIdx.x; i < n; i += gridDim.y*blockDim.x){
        float v = s[i];
        __nv_bfloat16 h = __float2bfloat16(v);
        wh[slot*SLOT_SZ + i] = h;
        wl[slot*SLOT_SZ + i] = __float2bfloat16(v - __bfloat162float(h));
    }
}
__global__ void conv_a(const float* __restrict__ s, __nv_bfloat16* __restrict__ h,
                       __nv_bfloat16* __restrict__ l, int n){
    for (int i = blockIdx.x*blockDim.x + threadIdx.x; i < n; i += gridDim.x*blockDim.x){
        float v = s[i];
        __nv_bfloat16 hh = __float2bfloat16(v);
        h[i] = hh;
        l[i] = __float2bfloat16(v - __bfloat162float(hh));
    }
}

// ---------------- bf16x3 HGEMM, 128x128 tile, cp.async pipelined -------------
// CTA: 128(M) x 128(N), 8 warps (4m x 2n), warp 32x64. BK=32, 3-stage, 1 barrier.
struct GemmP {
    const __nv_bfloat16 *AH[4], *AL[4];
    const __nv_bfloat16 *WH[4], *WL[4];
    float* C[4];
    __nv_bfloat16 *CH4[4], *CL4[4];
    int mode[4];
    __nv_bfloat16 *CH, *CL;
    const float* bias; const float* aux;
    int N; int K;
};

#define BPITCH 272
#define OFF_AL 10240
#define OFF_BH 20480
#define OFF_BL (20480+8704)
#define STG 37888
#define SMEM_TOT (3*STG)   /* 113664 */

template<int EPI>
__global__ __launch_bounds__(256,2)
void hgemm(GemmP p)
{
    extern __shared__ char smem[];
    const uint32_t sb = smem_u32(smem);
    const int tid = threadIdx.x;
    const int lane = tid&31, warp = tid>>5;
    const int wm = warp&3, wn = warp>>2;
    const int bm0 = blockIdx.x*128;
    const int N = p.N, K = p.K;
    const int NT = (N>=128) ? (N>>7) : 1;
    const int mi = blockIdx.y / NT;
    const int bn0 = (blockIdx.y % NT)*128;
    const __nv_bfloat16* __restrict__ AH = p.AH[mi];
    const __nv_bfloat16* __restrict__ AL = p.AL[mi];
    const __nv_bfloat16* __restrict__ WH = p.WH[mi];
    const __nv_bfloat16* __restrict__ WL = p.WL[mi];
    float* __restrict__ C = p.C[mi];
    const int nc = K>>5;

    float acc[2][8][4];
    #pragma unroll
    for (int mt=0;mt<2;mt++)
        #pragma unroll
        for (int j=0;j<8;j++)
            #pragma unroll
            for (int e=0;e<4;e++) acc[mt][j][e]=0.f;

    const int ar0 = tid>>1, aq0 = (tid&1)*2;
    const int br = tid>>3, bq = tid&7;
    const int bcol = bn0 + bq*16;
    const int bvalid = (bcol < N) ? 16 : 0;
    const int bcolc = (bcol < N) ? bcol : 0;

    auto issue = [&](int st){
        const uint32_t bs = sb + (uint32_t)((st%3)*STG);
        const size_t abase = (size_t)(bm0+ar0)*K + st*32;
        #pragma unroll
        for (int i=0;i<2;i++){
            const int qk = aq0 + i;
            const uint32_t dh = bs + ar0*80 + qk*16;
            CPA16(dh,          AH + abase + qk*8);
            CPA16(dh + OFF_AL, AL + abase + qk*8);
        }
        {
            const size_t wbase = (size_t)(st*32+br)*N + bcolc;
            const uint32_t dh = bs + OFF_BH + br*BPITCH + bq*32;
            CPA16Z(dh,                        WH + wbase,     bvalid);
            CPA16Z(dh + 16,                   WH + wbase + 8, bvalid);
            CPA16Z(dh + (OFF_BL-OFF_BH),      WL + wbase,     bvalid);
            CPA16Z(dh + (OFF_BL-OFF_BH) + 16, WL + wbase + 8, bvalid);
        }
        CPA_COMMIT();
    };

    {
        const int npro = (nc < 2) ? nc : 2;
        for (int s=0; s<npro; s++) issue(s);
    }

    for (int c=0; c<nc; c++){
        if (c == nc-1) CPA_WAIT0();
        else           CPA_WAIT1();
        __syncthreads();               // chunk c visible; slot (c-1)%3 free
        if (c+2 < nc) issue(c+2);

        const uint32_t sA  = sb + (uint32_t)((c%3)*STG);
        const uint32_t sAl = sA + OFF_AL;
        const uint32_t sB  = sA + OFF_BH;
        const uint32_t sBl = sA + OFF_BL;
        const uint32_t aro = (uint32_t)(wm*32 + (lane&15));
        const uint32_t bro = (uint32_t)(lane&15);

        #pragma unroll
        for (int s=0; s<2; s++){
            const uint32_t acol = (uint32_t)(s*16 + (lane>>4)*8)*2;
            uint32_t ah[2][4], al[2][4];
            #pragma unroll
            for (int mt=0; mt<2; mt++){
                const uint32_t ao = (aro + mt*16)*80 + acol;
                LDSM4(ah[mt], sA  + ao);
                LDSM4(al[mt], sAl + ao);
            }
            const uint32_t brow = (uint32_t)(s*16) + bro;
            #pragma unroll
            for (int j=0; j<8; j++){
                const uint32_t bo = brow*BPITCH + (uint32_t)(wn*64 + j*8)*2;
                uint32_t bh[2], bl[2];
                LDSM2T(bh, sB  + bo);
                LDSM2T(bl, sBl + bo);
                #pragma unroll
                for (int mt=0; mt<2; mt++){
                    MMA16816(acc[mt][j], ah[mt], bh);
                    MMA16816(acc[mt][j], al[mt], bh);
                    MMA16816(acc[mt][j], ah[mt], bl);
                }
            }
        }
    }

    const int g = lane>>2, tq = lane&3;

    if (EPI == 5){
        __syncthreads();
        float* l2g = (float*)smem;
        if (tid < 8){
            float lg = -3.4657359027997265f + (float)tid * (-0.39608410032853687f);
            l2g[tid] = log2f(1.f - expf(lg));
        }
        __syncthreads();
        const int mode = p.mode[mi];
        __nv_bfloat16* CH = p.CH4[mi];
        __nv_bfloat16* CL = p.CL4[mi];
        #pragma unroll
        for (int mt=0; mt<2; mt++){
            #pragma unroll
            for (int j=0; j<8; j++){
                const int col = bn0 + wn*64 + j*8 + tq*2;
                const float lg2 = l2g[col>>5];
                #pragma unroll
                for (int half=0; half<2; half++){
                    const int row = bm0 + wm*32 + mt*16 + g + half*8;
                    float v0 = acc[mt][j][2*half+0];
                    float v1 = acc[mt][j][2*half+1];
                    if (mode == 4){
                        *(float2*)(C + (size_t)row*N + col)
                            = make_float2(swish_f(v0), swish_f(v1));
                    } else {
                        if (mode == 1){
                            const float t = (float)((row & 255)>>3);
                            const float s = exp2f(t*lg2) * 0.17677669529663687f;
                            v0 *= s; v1 *= s;
                        } else if (mode == 2){
                            const float t = (float)((row & 255)>>3);
                            const float s = exp2f(-t*lg2);
                            v0 *= s; v1 *= s;
                        }
                        uint32_t lo, hi = pack2(v0, v1, lo);
                        *(uint32_t*)(CH + (size_t)row*N + col) = hi;
                        *(uint32_t*)(CL + (size_t)row*N + col) = lo;
                    }
                }
            }
        }
    } else {
        #pragma unroll
        for (int mt=0; mt<2; mt++){
            const int r0 = bm0 + wm*32 + mt*16 + g;
            #pragma unroll
            for (int j=0; j<8; j++){
                const int col = bn0 + wn*64 + j*8 + tq*2;
                if (col < N){
                    #pragma unroll
                    for (int half=0; half<2; half++){
                        const int row = r0 + half*8;
                        float v0 = acc[mt][j][2*half+0];
                        float v1 = acc[mt][j][2*half+1];
                        if (EPI==1){
                            if (p.bias){ v0 += p.bias[col]; v1 += p.bias[col+1]; }
                            v0 = gelu_tanh(v0); v1 = gelu_tanh(v1);
                            *(float2*)(C + (size_t)row*N + col) = make_float2(v0,v1);
                        } else if (EPI==2){
                            const float2 xa = *(const float2*)(p.aux + (size_t)row*N + col);
                            v0 = swish_f(v0)*xa.x; v1 = swish_f(v1)*xa.y;
                            uint32_t lo, hi = pack2(v0, v1, lo);
                            *(uint32_t*)(p.CH + (size_t)row*N + col) = hi;
                            *(uint32_t*)(p.CL + (size_t)row*N + col) = lo;
                        } else if (EPI==3){
                            v0 += p.bias[col]; v1 += p.bias[col+1];
                            *(float2*)(C + (size_t)row*N + col) = make_float2(v0,v1);
                        } else {
                            *(float2*)(C + (size_t)row*N + col) = make_float2(v0,v1);
                        }
                    }
                }
            }
        }
    }
}

// ---------------- tensor-core retention attention (cp.async K/V pipeline) ----
#define QROW 80
#define AQ_SZ (128*QROW)
#define AKV_SZ (64*QROW)
#define ABUF (4*AKV_SZ)
#define ATT_SMEM (2*AQ_SZ + 3*ABUF)

__global__ __launch_bounds__(256,2)
void attn_tc(const __nv_bfloat16* __restrict__ qh, const __nv_bfloat16* __restrict__ ql,
             const __nv_bfloat16* __restrict__ kh, const __nv_bfloat16* __restrict__ kl,
             const __nv_bfloat16* __restrict__ vh, const __nv_bfloat16* __restrict__ vl,
             const float* __restrict__ gsw,
             const float* __restrict__ gns, const float* __restrict__ gnb,
             __nv_bfloat16* __restrict__ zh, __nv_bfloat16* __restrict__ zl)
{
    extern __shared__ char smem[];
    const uint32_t sb = smem_u32(smem);

    const int b = blockIdx.z, h = blockIdx.y, rt = blockIdx.x;
    const int tid = threadIdx.x;
    const int lane = tid&31, wid = tid>>5;

    #pragma unroll
    for (int i=0;i<2;i++){
        const int idx = tid + i*256;
        const int row = idx>>2, seg = idx&3;
        const size_t gb = (size_t)(b*SEQ + rt*128 + row)*EMB + h*HEADD + seg*8;
        *(uint4*)(smem + row*QROW + seg*16)         = *(const uint4*)(qh + gb);
        *(uint4*)(smem + AQ_SZ + row*QROW + seg*16) = *(const uint4*)(ql + gb);
    }

    const int rowbase = rt*128 + wid*16;
    const int nchunks = 2*(rt+1);

    const int krow = tid>>2, kseg = tid&3;
    auto kv_issue = [&](int mc){
        const size_t gb = (size_t)(b*SEQ + mc*64 + krow)*EMB + h*HEADD + kseg*8;
        const uint32_t so = (uint32_t)(krow*QROW + kseg*16);
        const uint32_t bs = sb + 2*AQ_SZ + (uint32_t)((mc%3)*ABUF);
        CPA16(bs + so,            kh + gb);
        CPA16(bs + AKV_SZ + so,   kl + gb);
        CPA16(bs + 2*AKV_SZ + so, vh + gb);
        CPA16(bs + 3*AKV_SZ + so, vl + gb);
        CPA_COMMIT();
    };
    {
        const int npro = (nchunks < 2) ? nchunks : 2;
        for (int s=0; s<npro; s++) kv_issue(s);
    }
    __syncthreads();

    uint32_t qfh[2][4], qfl[2][4];
    {
        const uint32_t aro = (uint32_t)(wid*16 + (lane&15));
        #pragma unroll
        for (int kt=0; kt<2; kt++){
            const uint32_t ao = aro*QROW + (uint32_t)(kt*16 + (lane>>4)*8)*2;
            LDSM4(qfh[kt], sb + ao);
            LDSM4(qfl[kt], sb + AQ_SZ + ao);
        }
    }

    float oacc[4][4];
    #pragma unroll
    for (int jn=0;jn<4;jn++)
        #pragma unroll
        for (int e=0;e<4;e++) oacc[jn][e]=0.f;

    for (int mc=0; mc<nchunks; mc++){
        if (mc == nchunks-1) CPA_WAIT0();
        else                 CPA_WAIT1();
        __syncthreads();
        if (mc+2 < nchunks) kv_issue(mc+2);

        const int mbase = mc*64;
        if (mbase > rowbase + 15) continue;

        const uint32_t kvb = sb + 2*AQ_SZ + (uint32_t)((mc%3)*ABUF);
        const uint32_t kb  = kvb,             klb = kvb + AKV_SZ;
        const uint32_t vb  = kvb + 2*AKV_SZ,  vlb = kvb + 3*AKV_SZ;

        float sacc[8][4];
        #pragma unroll
        for (int j=0;j<8;j++)
            #pragma unroll
            for (int e=0;e<4;e++) sacc[j][e]=0.f;

        #pragma unroll
        for (int kt=0; kt<2; kt++){
            #pragma unroll
            for (int j=0; j<8; j++){
                const uint32_t addr = (uint32_t)(j*8 + (lane&7))*QROW
                                    + (uint32_t)((lane>>3)&1)*16 + (uint32_t)kt*32;
                uint32_t kfh[2], kfl[2];
                LDSM2(kfh, kb  + addr);
                LDSM2(kfl, klb + addr);
                MMA16816(sacc[j], qfh[kt], kfh);
                MMA16816(sacc[j], qfl[kt], kfh);
                MMA16816(sacc[j], qfh[kt], kfl);
            }
        }

        if (mbase + 63 > rowbase){
            const int nr = rowbase + (lane>>2);
            const int mcb = mbase + (lane&3)*2;
            #pragma unroll
            for (int j=0;j<8;j++){
                const int m0 = mcb + j*8;
                if (m0   > nr)   sacc[j][0]=0.f;
                if (m0+1 > nr)   sacc[j][1]=0.f;
                if (m0   > nr+8) sacc[j][2]=0.f;
                if (m0+1 > nr+8) sacc[j][3]=0.f;
            }
        }

        #pragma unroll
        for (int kt2=0; kt2<4; kt2++){
            uint32_t ah[4], al[4];
            ah[0] = pack2(sacc[2*kt2][0],   sacc[2*kt2][1],   al[0]);
            ah[1] = pack2(sacc[2*kt2][2],   sacc[2*kt2][3],   al[1]);
            ah[2] = pack2(sacc[2*kt2+1][0], sacc[2*kt2+1][1], al[2]);
            ah[3] = pack2(sacc[2*kt2+1][2], sacc[2*kt2+1][3], al[3]);
            #pragma unroll
            for (int jn=0; jn<4; jn++){
                const uint32_t addr = (uint32_t)(kt2*16 + (lane&15))*QROW
                                    + (uint32_t)(jn*8)*2;
                uint32_t vfh[2], vfl[2];
                LDSM2T(vfh, vb  + addr);
                LDSM2T(vfl, vlb + addr);
                MMA16816(oacc[jn], ah, vfh);
                MMA16816(oacc[jn], al, vfh);
                MMA16816(oacc[jn], ah, vfl);
            }
        }
    }

    const int gl = lane>>2, tq = lane&3;
    float sum0=0.f, sum1=0.f;
    #pragma unroll
    for (int jn=0;jn<4;jn++){
        sum0 += oacc[jn][0] + oacc[jn][1];
        sum1 += oacc[jn][2] + oacc[jn][3];
    }
    sum0 += __shfl_xor_sync(0xffffffffu, sum0, 1);
    sum0 += __shfl_xor_sync(0xffffffffu, sum0, 2);
    sum1 += __shfl_xor_sync(0xffffffffu, sum1, 1);
    sum1 += __shfl_xor_sync(0xffffffffu, sum1, 2);
    const float mu0 = sum0*(1.f/32.f), mu1 = sum1*(1.f/32.f);
    float v0=0.f, v1=0.f;
    #pragma unroll
    for (int jn=0;jn<4;jn++){
        float d0 = oacc[jn][0]-mu0, d1 = oacc[jn][1]-mu0;
        float d2 = oacc[jn][2]-mu1, d3 = oacc[jn][3]-mu1;
        v0 += d0*d0 + d1*d1;
        v1 += d2*d2 + d3*d3;
    }
    v0 += __shfl_xor_sync(0xffffffffu, v0, 1);
    v0 += __shfl_xor_sync(0xffffffffu, v0, 2);
    v1 += __shfl_xor_sync(0xffffffffu, v1, 1);
    v1 += __shfl_xor_sync(0xffffffffu, v1, 2);
    const float inv0 = rsqrtf(v0*(1.f/32.f) + 1e-5f);
    const float inv1 = rsqrtf(v1*(1.f/32.f) + 1e-5f);

    const int n0 = rowbase + gl;
    const size_t base0 = (size_t)(b*SEQ + n0)*EMB + h*HEADD;
    const size_t base1 = base0 + 8*EMB;
    #pragma unroll
    for (int jn=0;jn<4;jn++){
        const int c = jn*8 + tq*2;
        const float2 gs = *(const float2*)(gns + h*HEADD + c);
        const float2 gb2 = *(const float2*)(gnb + h*HEADD + c);
        float2 gg0 = *(const float2*)(gsw + base0 + c);
        float2 gg1 = *(const float2*)(gsw + base1 + c);
        float y0 = ((oacc[jn][0]-mu0)*inv0*gs.x + gb2.x) * gg0.x;
        float y1 = ((oacc[jn][1]-mu0)*inv0*gs.y + gb2.y) * gg0.y;
        float y2 = ((oacc[jn][2]-mu1)*inv1*gs.x + gb2.x) * gg1.x;
        float y3 = ((oacc[jn][3]-mu1)*inv1*gs.y + gb2.y) * gg1.y;
        uint32_t l01, h01 = pack2(y0, y1, l01);
        uint32_t l23, h23 = pack2(y2, y3, l23);
        *(uint32_t*)(zh + base0 + c) = h01;
        *(uint32_t*)(zl + base0 + c) = l01;
        *(uint32_t*)(zh + base1 + c) = h23;
        *(uint32_t*)(zl + base1 + c) = l23;
    }
}

// ---------------- rmsnorm (fused residual) + bf16 split out ------------------
__global__ __launch_bounds__(256)
void rmsnorm_kernel(const float* __restrict__ a, const float* __restrict__ b,
                    const float* __restrict__ scale, float* __restrict__ out,
                    __nv_bfloat16* __restrict__ outH, __nv_bfloat16* __restrict__ outL)
{
    const int row = blockIdx.x;
    const int tid = threadIdx.x;
    const size_t idx = (size_t)row*EMB + tid;
    float v = a[idx];
    if (b) v += b[idx];
    float sq = v*v;
    #pragma unroll
    for (int o=16;o;o>>=1) sq += __shfl_xor_sync(0xffffffffu, sq, o);
    __shared__ float ws[8];
    if ((tid & 31) == 0) ws[tid>>5] = sq;
    __syncthreads();
    float tot = 0.f;
    #pragma unroll
    for (int w=0; w<8; w++) tot += ws[w];
    float y = v * rsqrtf(tot*(1.f/256.f) + 1e-6f) * scale[tid];
    out[idx] = y;
    __nv_bfloat16 hh = __float2bfloat16(y);
    outH[idx] = hh;
    outL[idx] = __float2bfloat16(y - __bfloat162float(hh));
}

// ---------------- launcher ---------------------------------------------------
extern "C" void kernel_launch(void* const* d_in, const int* in_sizes, int n_in,
                              void* d_out, int out_size)
{
    (void)in_sizes; (void)n_in; (void)out_size;
    const float* action = (const float*)d_in[0];
    const float* obs    = (const float*)d_in[1];
    const float* w_enc  = (const float*)d_in[2];
    const float* ln0    = (const float*)d_in[3];
    const float* wq1    = (const float*)d_in[4];
    const float* wk1    = (const float*)d_in[5];
    const float* wv1    = (const float*)d_in[6];
    const float* wg1    = (const float*)d_in[7];
    const float* wo1    = (const float*)d_in[8];
    const float* gns1   = (const float*)d_in[9];
    const float* gnb1   = (const float*)d_in[10];
    const float* ln1    = (const float*)d_in[11];
    const float* wq2    = (const float*)d_in[12];
    const float* wk2    = (const float*)d_in[13];
    const float* wv2    = (const float*)d_in[14];
    const float* wg2    = (const float*)d_in[15];
    const float* wo2    = (const float*)d_in[16];
    const float* gns2   = (const float*)d_in[17];
    const float* gnb2   = (const float*)d_in[18];
    const float* ln2    = (const float*)d_in[19];
    const float* swg    = (const float*)d_in[20];
    const float* sw1    = (const float*)d_in[21];
    const float* sw2    = (const float*)d_in[22];
    const float* ln3    = (const float*)d_in[23];
    const float* hw1    = (const float*)d_in[24];
    const float* hb1    = (const float*)d_in[25];
    const float* hln    = (const float*)d_in[26];
    const float* hw2    = (const float*)d_in[27];
    const float* hb2    = (const float*)d_in[28];
    float* out = (float*)d_out;

    float *x,*gw,*tb,*zb;
    __nv_bfloat16 *xH,*xL,*oH,*oL,*zH,*zL,*qH,*qL,*kH,*kL,*vH,*vL,*aH,*aL,*wH,*wL;
    cudaGetSymbolAddress((void**)&x,  g_x);
    cudaGetSymbolAddress((void**)&gw, g_g);
    cudaGetSymbolAddress((void**)&tb, g_t);
    cudaGetSymbolAddress((void**)&zb, g_z);
    cudaGetSymbolAddress((void**)&xH, g_xH);
    cudaGetSymbolAddress((void**)&xL, g_xL);
    cudaGetSymbolAddress((void**)&oH, g_oH);
    cudaGetSymbolAddress((void**)&oL, g_oL);
    cudaGetSymbolAddress((void**)&zH, g_zH);
    cudaGetSymbolAddress((void**)&zL, g_zL);
    cudaGetSymbolAddress((void**)&qH, g_qH);
    cudaGetSymbolAddress((void**)&qL, g_qL);
    cudaGetSymbolAddress((void**)&kH, g_kH);
    cudaGetSymbolAddress((void**)&kL, g_kL);
    cudaGetSymbolAddress((void**)&vH, g_vH);
    cudaGetSymbolAddress((void**)&vL, g_vL);
    cudaGetSymbolAddress((void**)&aH, g_aH);
    cudaGetSymbolAddress((void**)&aL, g_aL);
    cudaGetSymbolAddress((void**)&wH, g_wH);
    cudaGetSymbolAddress((void**)&wL, g_wL);

    cudaFuncSetAttribute(hgemm<0>, cudaFuncAttributeMaxDynamicSharedMemorySize, SMEM_TOT);
    cudaFuncSetAttribute(hgemm<1>, cudaFuncAttributeMaxDynamicSharedMemorySize, SMEM_TOT);
    cudaFuncSetAttribute(hgemm<2>, cudaFuncAttributeMaxDynamicSharedMemorySize, SMEM_TOT);
    cudaFuncSetAttribute(hgemm<3>, cudaFuncAttributeMaxDynamicSharedMemorySize, SMEM_TOT);
    cudaFuncSetAttribute(hgemm<5>, cudaFuncAttributeMaxDynamicSharedMemorySize, SMEM_TOT);
    cudaFuncSetAttribute(attn_tc, cudaFuncAttributeMaxDynamicSharedMemorySize, ATT_SMEM);

    const float* wlist1[13] = {wq1,wk1,wv1,wg1,wo1,wq2,wk2,wv2,wg2,wo2,swg,sw1,sw2};
    ConvW cw{};
    for (int blk=0; blk<3; blk++)
        for (int j=0; j<13; j++){
            cw.src[blk*13+j] = wlist1[j] + (size_t)blk*EMB*EMB;
            cw.sz[blk*13+j] = EMB*EMB;
        }
    cw.src[39] = w_enc; cw.sz[39] = ADIM*EMB;
    cw.src[40] = hw1;   cw.sz[40] = EMB*EMB;
    cw.src[41] = hw2;   cw.sz[41] = EMB*ADIM;

    conv_w<<<dim3(NSLOT,32),256>>>(cw, wH, wL);
    conv_a<<<2048,256>>>(action, aH, aL, MROWS*ADIM);
    conv_a<<<4096,256>>>(obs, oH, oL, MROWS*EMB);

    auto WHs = [&](int slot){ return (const __nv_bfloat16*)(wH + (size_t)slot*SLOT_SZ); };
    auto WLs = [&](int slot){ return (const __nv_bfloat16*)(wL + (size_t)slot*SLOT_SZ); };

    auto mk1 = [&](const __nv_bfloat16* ah, const __nv_bfloat16* al, int slot,
                   float* c, const float* bias, const float* aux,
                   __nv_bfloat16* ch, __nv_bfloat16* cl, int N, int K){
        GemmP p{};
        for (int i=0;i<4;i++){ p.AH[i]=ah; p.AL[i]=al; p.WH[i]=WHs(slot); p.WL[i]=WLs(slot); p.C[i]=c; }
        p.bias=bias; p.aux=aux; p.CH=ch; p.CL=cl; p.N=N; p.K=K;
        return p;
    };

    const dim3 g1(MROWS/128, 2);      // one EMBxEMB gemm: 2 N-tiles of 128
    const dim3 g4(MROWS/128, 8);      // four mats
    const dim3 gHead(MROWS/128, 1);   // N=32
    const dim3 gAttn(SEQ/128, NHEAD, BATCH);

    // encoder
    hgemm<1><<<g1,256,SMEM_TOT>>>(mk1(aH, aL, 39, tb, nullptr, nullptr, nullptr, nullptr, EMB, ADIM));
    rmsnorm_kernel<<<MROWS,256>>>(tb, nullptr, ln0, x, xH, xL);

    for (int blk=0; blk<3; blk++){
        const int s0 = blk*13;
        const size_t vOff = (size_t)blk*EMB;

        // retention 1: q/k/v/g projections with fused scale/split/swish epilogue
        {
            GemmP p{};
            const int slots[4] = {s0+0, s0+1, s0+2, s0+3};
            __nv_bfloat16* chs[4] = {qH, kH, vH, nullptr};
            __nv_bfloat16* cls[4] = {qL, kL, vL, nullptr};
            const int modes[4] = {1, 2, 3, 4};
            for (int i=0;i<4;i++){
                p.AH[i]=xH; p.AL[i]=xL;
                p.WH[i]=WHs(slots[i]); p.WL[i]=WLs(slots[i]);
                p.C[i]=gw; p.CH4[i]=chs[i]; p.CL4[i]=cls[i]; p.mode[i]=modes[i];
            }
            p.N=EMB; p.K=EMB;
            hgemm<5><<<g4,256,SMEM_TOT>>>(p);
        }
        attn_tc<<<gAttn,256,ATT_SMEM>>>(qH, qL, kH, kL, vH, vL, gw, gns1+vOff, gnb1+vOff, zH, zL);
        hgemm<0><<<g1,256,SMEM_TOT>>>(mk1(zH, zL, s0+4, tb, nullptr, nullptr, nullptr, nullptr, EMB, EMB));
        rmsnorm_kernel<<<MROWS,256>>>(x, tb, ln1+vOff, x, xH, xL);

        // retention 2: q/g from obs, k/v from x
        {
            GemmP p{};
            const int slots[4] = {s0+5, s0+6, s0+7, s0+8};
            const __nv_bfloat16* ahs[4] = {oH, xH, xH, oH};
            const __nv_bfloat16* als[4] = {oL, xL, xL, oL};
            __nv_bfloat16* chs[4] = {qH, kH, vH, nullptr};
            __nv_bfloat16* cls[4] = {qL, kL, vL, nullptr};
            const int modes[4] = {1, 2, 3, 4};
            for (int i=0;i<4;i++){
                p.AH[i]=ahs[i]; p.AL[i]=als[i];
                p.WH[i]=WHs(slots[i]); p.WL[i]=WLs(slots[i]);
                p.C[i]=gw; p.CH4[i]=chs[i]; p.CL4[i]=cls[i]; p.mode[i]=modes[i];
            }
            p.N=EMB; p.K=EMB;
            hgemm<5><<<g4,256,SMEM_TOT>>>(p);
        }
        attn_tc<<<gAttn,256,ATT_SMEM>>>(qH, qL, kH, kL, vH, vL, gw, gns2+vOff, gnb2+vOff, zH, zL);
        hgemm<0><<<g1,256,SMEM_TOT>>>(mk1(zH, zL, s0+9, tb, nullptr, nullptr, nullptr, nullptr, EMB, EMB));
        rmsnorm_kernel<<<MROWS,256>>>(obs, tb, ln2+vOff, x, xH, xL);

        // swiglu
        hgemm<0><<<g1,256,SMEM_TOT>>>(mk1(xH, xL, s0+11, tb, nullptr, nullptr, nullptr, nullptr, EMB, EMB));
        hgemm<2><<<g1,256,SMEM_TOT>>>(mk1(xH, xL, s0+10, nullptr, nullptr, tb, zH, zL, EMB, EMB));
        hgemm<0><<<g1,256,SMEM_TOT>>>(mk1(zH, zL, s0+12, tb, nullptr, nullptr, nullptr, nullptr, EMB, EMB));
        rmsnorm_kernel<<<MROWS,256>>>(x, tb, ln3+vOff, x, xH, xL);
    }

    // head
    hgemm<1><<<g1,256,SMEM_TOT>>>(mk1(xH, xL, 40, tb, hb1, nullptr, nullptr, nullptr, EMB, EMB));
    rmsnorm_kernel<<<MROWS,256>>>(tb, nullptr, hln, zb, zH, zL);
    hgemm<3><<<gHead,256,SMEM_TOT>>>(mk1(zH, zL, 41, out, hb2, nullptr, nullptr, nullptr, ADIM, EMB));
}

// round 13
// speedup vs baseline: 1.4010x; 1.4010x over previous
#include <cuda_runtime.h>
#include <cuda_bf16.h>
#include <math.h>
#include <stdint.h>

#define BATCH 64
#define SEQ 256
#define EMB 256
#define NHEAD 8
#define HEADD 32
#define MROWS (BATCH*SEQ)   /* 16384 */
#define ADIM 32
#define NSLOT 42
#define SLOT_SZ 65536

// ---------------- scratch (device globals; no allocation allowed) ------------
__device__ float g_x[MROWS*EMB];
__device__ float g_g[MROWS*EMB];     // swish(gate), fp32
__device__ float g_t[MROWS*EMB];
__device__ float g_z[MROWS*EMB];
__device__ __nv_bfloat16 g_xH[MROWS*EMB], g_xL[MROWS*EMB];
__device__ __nv_bfloat16 g_oH[MROWS*EMB], g_oL[MROWS*EMB];
__device__ __nv_bfloat16 g_zH[MROWS*EMB], g_zL[MROWS*EMB];
__device__ __nv_bfloat16 g_qH[MROWS*EMB], g_qL[MROWS*EMB];
__device__ __nv_bfloat16 g_kH[MROWS*EMB], g_kL[MROWS*EMB];
__device__ __nv_bfloat16 g_vH[MROWS*EMB], g_vL[MROWS*EMB];
__device__ __nv_bfloat16 g_aH[MROWS*ADIM], g_aL[MROWS*ADIM];
__device__ __nv_bfloat16 g_wH[NSLOT*SLOT_SZ], g_wL[NSLOT*SLOT_SZ];

__device__ __forceinline__ float gelu_tanh(float x){
    float x3 = x*x*x;
    return 0.5f*x*(1.f + tanhf(0.7978845608028654f*(x + 0.044715f*x3)));
}
__device__ __forceinline__ float swish_f(float x){
    return x / (1.f + expf(-x));
}
__device__ __forceinline__ uint32_t smem_u32(const void* p){
    uint32_t a;
    asm("{ .reg .u64 t; cvta.to.shared.u64 t, %1; cvt.u32.u64 %0, t; }" : "=r"(a) : "l"(p));
    return a;
}
__device__ __forceinline__ uint32_t pack2(float a, float b, uint32_t& lo){
    __nv_bfloat16 ha = __float2bfloat16(a), hb = __float2bfloat16(b);
    __nv_bfloat16 la = __float2bfloat16(a - __bfloat162float(ha));
    __nv_bfloat16 lb = __float2bfloat16(b - __bfloat162float(hb));
    lo = (uint32_t)__bfloat16_as_ushort(la) | ((uint32_t)__bfloat16_as_ushort(lb)<<16);
    return (uint32_t)__bfloat16_as_ushort(ha) | ((uint32_t)__bfloat16_as_ushort(hb)<<16);
}

#define LDSM4(r, addr) \
    asm volatile("ldmatrix.sync.aligned.m8n8.x4.shared.b16 {%0,%1,%2,%3}, [%4];" \
        : "=r"((r)[0]),"=r"((r)[1]),"=r"((r)[2]),"=r"((r)[3]) : "r"(addr))
#define LDSM2(r, addr) \
    asm volatile("ldmatrix.sync.aligned.m8n8.x2.shared.b16 {%0,%1}, [%2];" \
        : "=r"((r)[0]),"=r"((r)[1]) : "r"(addr))
#define LDSM2T(r, addr) \
    asm volatile("ldmatrix.sync.aligned.m8n8.x2.trans.shared.b16 {%0,%1}, [%2];" \
        : "=r"((r)[0]),"=r"((r)[1]) : "r"(addr))
#define MMA16816(c, a, b) \
    asm volatile("mma.sync.aligned.m16n8k16.row.col.f32.bf16.bf16.f32 " \
        "{%0,%1,%2,%3}, {%4,%5,%6,%7}, {%8,%9}, {%0,%1,%2,%3};" \
        : "+f"((c)[0]),"+f"((c)[1]),"+f"((c)[2]),"+f"((c)[3]) \
        : "r"((a)[0]),"r"((a)[1]),"r"((a)[2]),"r"((a)[3]), "r"((b)[0]),"r"((b)[1]))
#define CPA16(dst, src) \
    asm volatile("cp.async.cg.shared.global [%0],[%1],16;" :: "r"(dst),"l"(src))
#define CPA16Z(dst, src, sz) \
    asm volatile("cp.async.cg.shared.global [%0],[%1],16,%2;" :: "r"(dst),"l"(src),"r"(sz))
#define CPA_COMMIT() asm volatile("cp.async.commit_group;" ::: "memory")
#define CPA_WAIT1()  asm volatile("cp.async.wait_group 1;" ::: "memory")
#define CPA_WAIT0()  asm volatile("cp.async.wait_group 0;" ::: "memory")

// ---------------- conversion kernels -----------------------------------------
struct ConvW { const float* src[NSLOT]; int sz[NSLOT]; };
__global__ void conv_w(ConvW cw, __nv_bfloat16* wh, __nv_bfloat16* wl){
    const int slot = blockIdx.x;
    const int n = cw.sz[slot];
    const float* s = cw.src[slot];
    for (int i = blockIdx.y*blockDim.x + threadIdx.x; i < n; i += gridDim.y*blockDim.x){
        float v = s[i];
        __nv_bfloat16 h = __float2bfloat16(v);
        wh[slot*SLOT_SZ + i] = h;
        wl[slot*SLOT_SZ + i] = __float2bfloat16(v - __bfloat162float(h));
    }
}
__global__ void conv_a(const float* __restrict__ s, __nv_bfloat16* __restrict__ h,
                       __nv_bfloat16* __restrict__ l, int n){
    for (int i = blockIdx.x*blockDim.x + threadIdx.x; i < n; i += gridDim.x*blockDim.x){
        float v = s[i];
        __nv_bfloat16 hh = __float2bfloat16(v);
        h[i] = hh;
        l[i] = __float2bfloat16(v - __bfloat162float(hh));
    }
}

// ---------------- bf16x3 HGEMM, 128x64, cp.async, strength-reduced -----------
struct GemmP {
    const __nv_bfloat16 *AH[4], *AL[4];
    const __nv_bfloat16 *WH[4], *WL[4];
    float* C[4];
    __nv_bfloat16 *CH4[4], *CL4[4];
    int mode[4];
    __nv_bfloat16 *CH, *CL;
    const float* bias; const float* aux;
    int N; int K;
};

#define STG 29696
#define OFF_AL 10240
#define OFF_BH 20480
#define OFF_BL 25088
#define SMEM_TOT (3*STG)

template<int EPI>
__global__ __launch_bounds__(256,2)
void hgemm(GemmP p)
{
    extern __shared__ char smem[];
    const uint32_t sb = smem_u32(smem);
    const uint32_t sbEnd = sb + 3*STG;
    const int tid = threadIdx.x;
    const int lane = tid&31, warp = tid>>5;
    const int wm = warp&3, wn = warp>>2;
    const int bm0 = blockIdx.x*128;
    const int N = p.N, K = p.K;
    const int NT = (N>=64) ? (N>>6) : 1;
    const int mi = blockIdx.y / NT;
    const int bn0 = (blockIdx.y % NT)*64;
    const __nv_bfloat16* __restrict__ AH = p.AH[mi];
    const __nv_bfloat16* __restrict__ AL = p.AL[mi];
    const __nv_bfloat16* __restrict__ WH = p.WH[mi];
    const __nv_bfloat16* __restrict__ WL = p.WL[mi];
    float* __restrict__ C = p.C[mi];
    const int nc = K>>5;

    float acc[2][4][4];
    #pragma unroll
    for (int mt=0;mt<2;mt++)
        #pragma unroll
        for (int j=0;j<4;j++)
            #pragma unroll
            for (int e=0;e<4;e++) acc[mt][j][e]=0.f;

    const int ar0 = tid>>1, aq0 = (tid&1)*2;
    const int br = tid>>3, bq = tid&7;
    const int bcol = bn0 + bq*8;
    const int bvalid = (bcol < N) ? 16 : 0;
    const int bcolc = (bcol < N) ? bcol : 0;

    // strength-reduced producer state: pointers advance by constants
    const __nv_bfloat16* apH = AH + (size_t)(bm0+ar0)*K + aq0*8;
    const __nv_bfloat16* apL = AL + (size_t)(bm0+ar0)*K + aq0*8;
    const __nv_bfloat16* wpH = WH + (size_t)br*N + bcolc;
    const __nv_bfloat16* wpL = WL + (size_t)br*N + bcolc;
    const size_t wStep = (size_t)32*N;
    uint32_t isb = sb;
    const uint32_t aDst = (uint32_t)(ar0*80 + aq0*16);
    const uint32_t bDst = (uint32_t)(OFF_BH + br*144 + bq*16);

    auto issue = [&](){
        const uint32_t dh = isb + aDst;
        CPA16(dh,               apH);
        CPA16(dh + 16,          apH + 8);
        CPA16(dh + OFF_AL,      apL);
        CPA16(dh + OFF_AL + 16, apL + 8);
        const uint32_t dB = isb + bDst;
        CPA16Z(dB,                   wpH, bvalid);
        CPA16Z(dB + (OFF_BL-OFF_BH), wpL, bvalid);
        CPA_COMMIT();
        apH += 32; apL += 32; wpH += wStep; wpL += wStep;
        isb += STG; if (isb == sbEnd) isb = sb;
    };

    {
        const int npro = (nc < 2) ? nc : 2;
        for (int s=0; s<npro; s++) issue();
    }

    const uint32_t aro = (uint32_t)(wm*32 + (lane&15));
    const uint32_t bro = (uint32_t)(lane&15);
    uint32_t csb = sb;

    for (int c=0; c<nc; c++){
        if (c == nc-1) CPA_WAIT0();
        else           CPA_WAIT1();
        __syncthreads();               // chunk c visible; slot (c-1)%3 free
        if (c+2 < nc) issue();

        const uint32_t sA  = csb;
        const uint32_t sAl = csb + OFF_AL;
        const uint32_t sB  = csb + OFF_BH;
        const uint32_t sBl = csb + OFF_BL;
        csb += STG; if (csb == sbEnd) csb = sb;

        #pragma unroll
        for (int s=0; s<2; s++){
            const uint32_t acol = (uint32_t)(s*16 + (lane>>4)*8)*2;
            uint32_t ah[2][4], al[2][4], bh[4][2], bl[4][2];
            #pragma unroll
            for (int mt=0; mt<2; mt++){
                const uint32_t ao = (aro + mt*16)*80 + acol;
                LDSM4(ah[mt], sA  + ao);
                LDSM4(al[mt], sAl + ao);
            }
            const uint32_t brow = (uint32_t)(s*16) + bro;
            #pragma unroll
            for (int j=0; j<4; j++){
                const uint32_t bo = brow*144 + (uint32_t)(wn*32 + j*8)*2;
                LDSM2T(bh[j], sB  + bo);
                LDSM2T(bl[j], sBl + bo);
            }
            #pragma unroll
            for (int mt=0; mt<2; mt++)
                #pragma unroll
                for (int j=0; j<4; j++)
                    MMA16816(acc[mt][j], ah[mt], bh[j]);
            #pragma unroll
            for (int mt=0; mt<2; mt++)
                #pragma unroll
                for (int j=0; j<4; j++)
                    MMA16816(acc[mt][j], ah[mt], bl[j]);
            #pragma unroll
            for (int mt=0; mt<2; mt++)
                #pragma unroll
                for (int j=0; j<4; j++)
                    MMA16816(acc[mt][j], al[mt], bh[j]);
        }
    }

    const int g = lane>>2, tq = lane&3;

    if (EPI == 5){
        __syncthreads();
        float* l2g = (float*)smem;
        if (tid < 8){
            float lg = -3.4657359027997265f + (float)tid * (-0.39608410032853687f);
            l2g[tid] = log2f(1.f - expf(lg));
        }
        __syncthreads();
        const int mode = p.mode[mi];
        __nv_bfloat16* CH = p.CH4[mi];
        __nv_bfloat16* CL = p.CL4[mi];
        #pragma unroll
        for (int mt=0; mt<2; mt++){
            #pragma unroll
            for (int j=0; j<4; j++){
                const int col = bn0 + wn*32 + j*8 + tq*2;
                const float lg2 = l2g[col>>5];
                #pragma unroll
                for (int half=0; half<2; half++){
                    const int row = bm0 + wm*32 + mt*16 + g + half*8;
                    float v0 = acc[mt][j][2*half+0];
                    float v1 = acc[mt][j][2*half+1];
                    if (mode == 4){
                        *(float2*)(C + (size_t)row*N + col)
                            = make_float2(swish_f(v0), swish_f(v1));
                    } else {
                        if (mode == 1){
                            const float t = (float)((row & 255)>>3);
                            const float s = exp2f(t*lg2) * 0.17677669529663687f;
                            v0 *= s; v1 *= s;
                        } else if (mode == 2){
                            const float t = (float)((row & 255)>>3);
                            const float s = exp2f(-t*lg2);
                            v0 *= s; v1 *= s;
                        }
                        uint32_t lo, hi = pack2(v0, v1, lo);
                        *(uint32_t*)(CH + (size_t)row*N + col) = hi;
                        *(uint32_t*)(CL + (size_t)row*N + col) = lo;
                    }
                }
            }
        }
    } else {
        #pragma unroll
        for (int mt=0; mt<2; mt++){
            const int r0 = bm0 + wm*32 + mt*16 + g;
            #pragma unroll
            for (int j=0; j<4; j++){
                const int col = bn0 + wn*32 + j*8 + tq*2;
                if (col < N){
                    #pragma unroll
                    for (int half=0; half<2; half++){
                        const int row = r0 + half*8;
                        float v0 = acc[mt][j][2*half+0];
                        float v1 = acc[mt][j][2*half+1];
                        if (EPI==1){
                            if (p.bias){ v0 += p.bias[col]; v1 += p.bias[col+1]; }
                            v0 = gelu_tanh(v0); v1 = gelu_tanh(v1);
                            *(float2*)(C + (size_t)row*N + col) = make_float2(v0,v1);
                        } else if (EPI==2){
                            const float2 xa = *(const float2*)(p.aux + (size_t)row*N + col);
                            v0 = swish_f(v0)*xa.x; v1 = swish_f(v1)*xa.y;
                            uint32_t lo, hi = pack2(v0, v1, lo);
                            *(uint32_t*)(p.CH + (size_t)row*N + col) = hi;
                            *(uint32_t*)(p.CL + (size_t)row*N + col) = lo;
                        } else if (EPI==3){
                            v0 += p.bias[col]; v1 += p.bias[col+1];
                            *(float2*)(C + (size_t)row*N + col) = make_float2(v0,v1);
                        } else {
                            *(float2*)(C + (size_t)row*N + col) = make_float2(v0,v1);
                        }
                    }
                }
            }
        }
    }
}

// ---------------- tensor-core retention attention (strength-reduced) ---------
#define QROW 80
#define AQ_SZ (128*QROW)
#define AKV_SZ (64*QROW)
#define ABUF (4*AKV_SZ)
#define ATT_SMEM (2*AQ_SZ + 3*ABUF)

__global__ __launch_bounds__(256,2)
void attn_tc(const __nv_bfloat16* __restrict__ qh, const __nv_bfloat16* __restrict__ ql,
             const __nv_bfloat16* __restrict__ kh, const __nv_bfloat16* __restrict__ kl,
             const __nv_bfloat16* __restrict__ vh, const __nv_bfloat16* __restrict__ vl,
             const float* __restrict__ gsw,
             const float* __restrict__ gns, const float* __restrict__ gnb,
             __nv_bfloat16* __restrict__ zh, __nv_bfloat16* __restrict__ zl)
{
    extern __shared__ char smem[];
    const uint32_t sb = smem_u32(smem);

    const int b = blockIdx.z, h = blockIdx.y, rt = blockIdx.x;
    const int tid = threadIdx.x;
    const int lane = tid&31, wid = tid>>5;

    #pragma unroll
    for (int i=0;i<2;i++){
        const int idx = tid + i*256;
        const int row = idx>>2, seg = idx&3;
        const size_t gb = (size_t)(b*SEQ + rt*128 + row)*EMB + h*HEADD + seg*8;
        *(uint4*)(smem + row*QROW + seg*16)         = *(const uint4*)(qh + gb);
        *(uint4*)(smem + AQ_SZ + row*QROW + seg*16) = *(const uint4*)(ql + gb);
    }

    const int rowbase = rt*128 + wid*16;
    const int nchunks = 2*(rt+1);

    // strength-reduced K/V producer
    const int krow = tid>>2, kseg = tid&3;
    {
        // nothing
    }
    const size_t kv0 = (size_t)(b*SEQ + krow)*EMB + h*HEADD + kseg*8;
    const __nv_bfloat16* kpH = kh + kv0;
    const __nv_bfloat16* kpL = kl + kv0;
    const __nv_bfloat16* vpH = vh + kv0;
    const __nv_bfloat16* vpL = vl + kv0;
    const size_t kvStep = (size_t)64*EMB;
    const uint32_t kvDst = (uint32_t)(krow*QROW + kseg*16);
    uint32_t ksb = sb + 2*AQ_SZ;
    const uint32_t ksbEnd = sb + 2*AQ_SZ + 3*ABUF;

    auto kv_issue = [&](){
        const uint32_t d = ksb + kvDst;
        CPA16(d,            kpH);
        CPA16(d + AKV_SZ,   kpL);
        CPA16(d + 2*AKV_SZ, vpH);
        CPA16(d + 3*AKV_SZ, vpL);
        CPA_COMMIT();
        kpH += kvStep; kpL += kvStep; vpH += kvStep; vpL += kvStep;
        ksb += ABUF; if (ksb == ksbEnd) ksb = sb + 2*AQ_SZ;
    };
    {
        const int npro = (nchunks < 2) ? nchunks : 2;
        for (int s=0; s<npro; s++) kv_issue();
    }
    __syncthreads();

    uint32_t qfh[2][4], qfl[2][4];
    {
        const uint32_t aro = (uint32_t)(wid*16 + (lane&15));
        #pragma unroll
        for (int kt=0; kt<2; kt++){
            const uint32_t ao = aro*QROW + (uint32_t)(kt*16 + (lane>>4)*8)*2;
            LDSM4(qfh[kt], sb + ao);
            LDSM4(qfl[kt], sb + AQ_SZ + ao);
        }
    }

    float oacc[4][4];
    #pragma unroll
    for (int jn=0;jn<4;jn++)
        #pragma unroll
        for (int e=0;e<4;e++) oacc[jn][e]=0.f;

    uint32_t csb = sb + 2*AQ_SZ;

    for (int mc=0; mc<nchunks; mc++){
        if (mc == nchunks-1) CPA_WAIT0();
        else                 CPA_WAIT1();
        __syncthreads();
        if (mc+2 < nchunks) kv_issue();

        const uint32_t kvb = csb;
        csb += ABUF; if (csb == ksbEnd) csb = sb + 2*AQ_SZ;

        const int mbase = mc*64;
        if (mbase > rowbase + 15) continue;

        const uint32_t kb  = kvb,             klb = kvb + AKV_SZ;
        const uint32_t vb  = kvb + 2*AKV_SZ,  vlb = kvb + 3*AKV_SZ;

        float sacc[8][4];
        #pragma unroll
        for (int j=0;j<8;j++)
            #pragma unroll
            for (int e=0;e<4;e++) sacc[j][e]=0.f;

        #pragma unroll
        for (int kt=0; kt<2; kt++){
            #pragma unroll
            for (int j=0; j<8; j++){
                const uint32_t addr = (uint32_t)(j*8 + (lane&7))*QROW
                                    + (uint32_t)((lane>>3)&1)*16 + (uint32_t)kt*32;
                uint32_t kfh[2], kfl[2];
                LDSM2(kfh, kb  + addr);
                LDSM2(kfl, klb + addr);
                MMA16816(sacc[j], qfh[kt], kfh);
                MMA16816(sacc[j], qfl[kt], kfh);
                MMA16816(sacc[j], qfh[kt], kfl);
            }
        }

        if (mbase + 63 > rowbase){
            const int nr = rowbase + (lane>>2);
            const int mcb = mbase + (lane&3)*2;
            #pragma unroll
            for (int j=0;j<8;j++){
                const int m0 = mcb + j*8;
                if (m0   > nr)   sacc[j][0]=0.f;
                if (m0+1 > nr)   sacc[j][1]=0.f;
                if (m0   > nr+8) sacc[j][2]=0.f;
                if (m0+1 > nr+8) sacc[j][3]=0.f;
            }
        }

        #pragma unroll
        for (int kt2=0; kt2<4; kt2++){
            uint32_t ah[4], al[4];
            ah[0] = pack2(sacc[2*kt2][0],   sacc[2*kt2][1],   al[0]);
            ah[1] = pack2(sacc[2*kt2][2],   sacc[2*kt2][3],   al[1]);
            ah[2] = pack2(sacc[2*kt2+1][0], sacc[2*kt2+1][1], al[2]);
            ah[3] = pack2(sacc[2*kt2+1][2], sacc[2*kt2+1][3], al[3]);
            #pragma unroll
            for (int jn=0; jn<4; jn++){
                const uint32_t addr = (uint32_t)(kt2*16 + (lane&15))*QROW
                                    + (uint32_t)(jn*8)*2;
                uint32_t vfh[2], vfl[2];
                LDSM2T(vfh, vb  + addr);
                LDSM2T(vfl, vlb + addr);
                MMA16816(oacc[jn], ah, vfh);
                MMA16816(oacc[jn], al, vfh);
                MMA16816(oacc[jn], ah, vfl);
            }
        }
    }

    const int gl = lane>>2, tq = lane&3;
    float sum0=0.f, sum1=0.f;
    #pragma unroll
    for (int jn=0;jn<4;jn++){
        sum0 += oacc[jn][0] + oacc[jn][1];
        sum1 += oacc[jn][2] + oacc[jn][3];
    }
    sum0 += __shfl_xor_sync(0xffffffffu, sum0, 1);
    sum0 += __shfl_xor_sync(0xffffffffu, sum0, 2);
    sum1 += __shfl_xor_sync(0xffffffffu, sum1, 1);
    sum1 += __shfl_xor_sync(0xffffffffu, sum1, 2);
    const float mu0 = sum0*(1.f/32.f), mu1 = sum1*(1.f/32.f);
    float v0=0.f, v1=0.f;
    #pragma unroll
    for (int jn=0;jn<4;jn++){
        float d0 = oacc[jn][0]-mu0, d1 = oacc[jn][1]-mu0;
        float d2 = oacc[jn][2]-mu1, d3 = oacc[jn][3]-mu1;
        v0 += d0*d0 + d1*d1;
        v1 += d2*d2 + d3*d3;
    }
    v0 += __shfl_xor_sync(0xffffffffu, v0, 1);
    v0 += __shfl_xor_sync(0xffffffffu, v0, 2);
    v1 += __shfl_xor_sync(0xffffffffu, v1, 1);
    v1 += __shfl_xor_sync(0xffffffffu, v1, 2);
    const float inv0 = rsqrtf(v0*(1.f/32.f) + 1e-5f);
    const float inv1 = rsqrtf(v1*(1.f/32.f) + 1e-5f);

    const int n0 = rowbase + gl;
    const size_t base0 = (size_t)(b*SEQ + n0)*EMB + h*HEADD;
    const size_t base1 = base0 + 8*EMB;
    #pragma unroll
    for (int jn=0;jn<4;jn++){
        const int c = jn*8 + tq*2;
        const float2 gs = *(const float2*)(gns + h*HEADD + c);
        const float2 gb2 = *(const float2*)(gnb + h*HEADD + c);
        float2 gg0 = *(const float2*)(gsw + base0 + c);
        float2 gg1 = *(const float2*)(gsw + base1 + c);
        float y0 = ((oacc[jn][0]-mu0)*inv0*gs.x + gb2.x) * gg0.x;
        float y1 = ((oacc[jn][1]-mu0)*inv0*gs.y + gb2.y) * gg0.y;
        float y2 = ((oacc[jn][2]-mu1)*inv1*gs.x + gb2.x) * gg1.x;
        float y3 = ((oacc[jn][3]-mu1)*inv1*gs.y + gb2.y) * gg1.y;
        uint32_t l01, h01 = pack2(y0, y1, l01);
        uint32_t l23, h23 = pack2(y2, y3, l23);
        *(uint32_t*)(zh + base0 + c) = h01;
        *(uint32_t*)(zl + base0 + c) = l01;
        *(uint32_t*)(zh + base1 + c) = h23;
        *(uint32_t*)(zl + base1 + c) = l23;
    }
}

// ---------------- rmsnorm (fused residual) + bf16 split out ------------------
__global__ __launch_bounds__(256)
void rmsnorm_kernel(const float* __restrict__ a, const float* __restrict__ b,
                    const float* __restrict__ scale, float* __restrict__ out,
                    __nv_bfloat16* __restrict__ outH, __nv_bfloat16* __restrict__ outL)
{
    const int row = blockIdx.x;
    const int tid = threadIdx.x;
    const size_t idx = (size_t)row*EMB + tid;
    float v = a[idx];
    if (b) v += b[idx];
    float sq = v*v;
    #pragma unroll
    for (int o=16;o;o>>=1) sq += __shfl_xor_sync(0xffffffffu, sq, o);
    __shared__ float ws[8];
    if ((tid & 31) == 0) ws[tid>>5] = sq;
    __syncthreads();
    float tot = 0.f;
    #pragma unroll
    for (int w=0; w<8; w++) tot += ws[w];
    float y = v * rsqrtf(tot*(1.f/256.f) + 1e-6f) * scale[tid];
    out[idx] = y;
    __nv_bfloat16 hh = __float2bfloat16(y);
    outH[idx] = hh;
    outL[idx] = __float2bfloat16(y - __bfloat162float(hh));
}

// ---------------- launcher ---------------------------------------------------
extern "C" void kernel_launch(void* const* d_in, const int* in_sizes, int n_in,
                              void* d_out, int out_size)
{
    (void)in_sizes; (void)n_in; (void)out_size;
    const float* action = (const float*)d_in[0];
    const float* obs    = (const float*)d_in[1];
    const float* w_enc  = (const float*)d_in[2];
    const float* ln0    = (const float*)d_in[3];
    const float* wq1    = (const float*)d_in[4];
    const float* wk1    = (const float*)d_in[5];
    const float* wv1    = (const float*)d_in[6];
    const float* wg1    = (const float*)d_in[7];
    const float* wo1    = (const float*)d_in[8];
    const float* gns1   = (const float*)d_in[9];
    const float* gnb1   = (const float*)d_in[10];
    const float* ln1    = (const float*)d_in[11];
    const float* wq2    = (const float*)d_in[12];
    const float* wk2    = (const float*)d_in[13];
    const float* wv2    = (const float*)d_in[14];
    const float* wg2    = (const float*)d_in[15];
    const float* wo2    = (const float*)d_in[16];
    const float* gns2   = (const float*)d_in[17];
    const float* gnb2   = (const float*)d_in[18];
    const float* ln2    = (const float*)d_in[19];
    const float* swg    = (const float*)d_in[20];
    const float* sw1    = (const float*)d_in[21];
    const float* sw2    = (const float*)d_in[22];
    const float* ln3    = (const float*)d_in[23];
    const float* hw1    = (const float*)d_in[24];
    const float* hb1    = (const float*)d_in[25];
    const float* hln    = (const float*)d_in[26];
    const float* hw2    = (const float*)d_in[27];
    const float* hb2    = (const float*)d_in[28];
    float* out = (float*)d_out;

    float *x,*gw,*tb,*zb;
    __nv_bfloat16 *xH,*xL,*oH,*oL,*zH,*zL,*qH,*qL,*kH,*kL,*vH,*vL,*aH,*aL,*wH,*wL;
    cudaGetSymbolAddress((void**)&x,  g_x);
    cudaGetSymbolAddress((void**)&gw, g_g);
    cudaGetSymbolAddress((void**)&tb, g_t);
    cudaGetSymbolAddress((void**)&zb, g_z);
    cudaGetSymbolAddress((void**)&xH, g_xH);
    cudaGetSymbolAddress((void**)&xL, g_xL);
    cudaGetSymbolAddress((void**)&oH, g_oH);
    cudaGetSymbolAddress((void**)&oL, g_oL);
    cudaGetSymbolAddress((void**)&zH, g_zH);
    cudaGetSymbolAddress((void**)&zL, g_zL);
    cudaGetSymbolAddress((void**)&qH, g_qH);
    cudaGetSymbolAddress((void**)&qL, g_qL);
    cudaGetSymbolAddress((void**)&kH, g_kH);
    cudaGetSymbolAddress((void**)&kL, g_kL);
    cudaGetSymbolAddress((void**)&vH, g_vH);
    cudaGetSymbolAddress((void**)&vL, g_vL);
    cudaGetSymbolAddress((void**)&aH, g_aH);
    cudaGetSymbolAddress((void**)&aL, g_aL);
    cudaGetSymbolAddress((void**)&wH, g_wH);
    cudaGetSymbolAddress((void**)&wL, g_wL);

    cudaFuncSetAttribute(hgemm<0>, cudaFuncAttributeMaxDynamicSharedMemorySize, SMEM_TOT);
    cudaFuncSetAttribute(hgemm<1>, cudaFuncAttributeMaxDynamicSharedMemorySize, SMEM_TOT);
    cudaFuncSetAttribute(hgemm<2>, cudaFuncAttributeMaxDynamicSharedMemorySize, SMEM_TOT);
    cudaFuncSetAttribute(hgemm<3>, cudaFuncAttributeMaxDynamicSharedMemorySize, SMEM_TOT);
    cudaFuncSetAttribute(hgemm<5>, cudaFuncAttributeMaxDynamicSharedMemorySize, SMEM_TOT);
    cudaFuncSetAttribute(attn_tc, cudaFuncAttributeMaxDynamicSharedMemorySize, ATT_SMEM);

    const float* wlist1[13] = {wq1,wk1,wv1,wg1,wo1,wq2,wk2,wv2,wg2,wo2,swg,sw1,sw2};
    ConvW cw{};
    for (int blk=0; blk<3; blk++)
        for (int j=0; j<13; j++){
            cw.src[blk*13+j] = wlist1[j] + (size_t)blk*EMB*EMB;
            cw.sz[blk*13+j] = EMB*EMB;
        }
    cw.src[39] = w_enc; cw.sz[39] = ADIM*EMB;
    cw.src[40] = hw1;   cw.sz[40] = EMB*EMB;
    cw.src[41] = hw2;   cw.sz[41] = EMB*ADIM;

    conv_w<<<dim3(NSLOT,32),256>>>(cw, wH, wL);
    conv_a<<<2048,256>>>(action, aH, aL, MROWS*ADIM);
    conv_a<<<4096,256>>>(obs, oH, oL, MROWS*EMB);

    auto WHs = [&](int slot){ return (const __nv_bfloat16*)(wH + (size_t)slot*SLOT_SZ); };
    auto WLs = [&](int slot){ return (const __nv_bfloat16*)(wL + (size_t)slot*SLOT_SZ); };

    auto mk1 = [&](const __nv_bfloat16* ah, const __nv_bfloat16* al, int slot,
                   float* c, const float* bias, const float* aux,
                   __nv_bfloat16* ch, __nv_bfloat16* cl, int N, int K){
        GemmP p{};
        for (int i=0;i<4;i++){ p.AH[i]=ah; p.AL[i]=al; p.WH[i]=WHs(slot); p.WL[i]=WLs(slot); p.C[i]=c; }
        p.bias=bias; p.aux=aux; p.CH=ch; p.CL=cl; p.N=N; p.K=K;
        return p;
    };

    const dim3 g1(MROWS/128, 4);
    const dim3 g4(MROWS/128, 16);
    const dim3 gHead(MROWS/128, 1);
    const dim3 gAttn(SEQ/128, NHEAD, BATCH);

    // encoder
    hgemm<1><<<g1,256,SMEM_TOT>>>(mk1(aH, aL, 39, tb, nullptr, nullptr, nullptr, nullptr, EMB, ADIM));
    rmsnorm_kernel<<<MROWS,256>>>(tb, nullptr, ln0, x, xH, xL);

    for (int blk=0; blk<3; blk++){
        const int s0 = blk*13;
        const size_t vOff = (size_t)blk*EMB;

        // retention 1: q/k/v/g projections with fused scale/split/swish epilogue
        {
            GemmP p{};
            const int slots[4] = {s0+0, s0+1, s0+2, s0+3};
            __nv_bfloat16* chs[4] = {qH, kH, vH, nullptr};
            __nv_bfloat16* cls[4] = {qL, kL, vL, nullptr};
            const int modes[4] = {1, 2, 3, 4};
            for (int i=0;i<4;i++){
                p.AH[i]=xH; p.AL[i]=xL;
                p.WH[i]=WHs(slots[i]); p.WL[i]=WLs(slots[i]);
                p.C[i]=gw; p.CH4[i]=chs[i]; p.CL4[i]=cls[i]; p.mode[i]=modes[i];
            }
            p.N=EMB; p.K=EMB;
            hgemm<5><<<g4,256,SMEM_TOT>>>(p);
        }
        attn_tc<<<gAttn,256,ATT_SMEM>>>(qH, qL, kH, kL, vH, vL, gw, gns1+vOff, gnb1+vOff, zH, zL);
        hgemm<0><<<g1,256,SMEM_TOT>>>(mk1(zH, zL, s0+4, tb, nullptr, nullptr, nullptr, nullptr, EMB, EMB));
        rmsnorm_kernel<<<MROWS,256>>>(x, tb, ln1+vOff, x, xH, xL);

        // retention 2: q/g from obs, k/v from x
        {
            GemmP p{};
            const int slots[4] = {s0+5, s0+6, s0+7, s0+8};
            const __nv_bfloat16* ahs[4] = {oH, xH, xH, oH};
            const __nv_bfloat16* als[4] = {oL, xL, xL, oL};
            __nv_bfloat16* chs[4] = {qH, kH, vH, nullptr};
            __nv_bfloat16* cls[4] = {qL, kL, vL, nullptr};
            const int modes[4] = {1, 2, 3, 4};
            for (int i=0;i<4;i++){
                p.AH[i]=ahs[i]; p.AL[i]=als[i];
                p.WH[i]=WHs(slots[i]); p.WL[i]=WLs(slots[i]);
                p.C[i]=gw; p.CH4[i]=chs[i]; p.CL4[i]=cls[i]; p.mode[i]=modes[i];
            }
            p.N=EMB; p.K=EMB;
            hgemm<5><<<g4,256,SMEM_TOT>>>(p);
        }
        attn_tc<<<gAttn,256,ATT_SMEM>>>(qH, qL, kH, kL, vH, vL, gw, gns2+vOff, gnb2+vOff, zH, zL);
        hgemm<0><<<g1,256,SMEM_TOT>>>(mk1(zH, zL, s0+9, tb, nullptr, nullptr, nullptr, nullptr, EMB, EMB));
        rmsnorm_kernel<<<MROWS,256>>>(obs, tb, ln2+vOff, x, xH, xL);

        // swiglu
        hgemm<0><<<g1,256,SMEM_TOT>>>(mk1(xH, xL, s0+11, tb, nullptr, nullptr, nullptr, nullptr, EMB, EMB));
        hgemm<2><<<g1,256,SMEM_TOT>>>(mk1(xH, xL, s0+10, nullptr, nullptr, tb, zH, zL, EMB, EMB));
        hgemm<0><<<g1,256,SMEM_TOT>>>(mk1(zH, zL, s0+12, tb, nullptr, nullptr, nullptr, nullptr, EMB, EMB));
        rmsnorm_kernel<<<MROWS,256>>>(x, tb, ln3+vOff, x, xH, xL);
    }

    // head
    hgemm<1><<<g1,256,SMEM_TOT>>>(mk1(xH, xL, 40, tb, hb1, nullptr, nullptr, nullptr, EMB, EMB));
    rmsnorm_kernel<<<MROWS,256>>>(tb, nullptr, hln, zb, zH, zL);
    hgemm<3><<<gHead,256,SMEM_TOT>>>(mk1(zH, zL, 41, out, hb2, nullptr, nullptr, nullptr, ADIM, EMB));
}

// round 14
// speedup vs baseline: 1.4174x; 1.0117x over previous
#include <cuda_runtime.h>
#include <cuda_bf16.h>
#include <math.h>
#include <stdint.h>

#define BATCH 64
#define SEQ 256
#define EMB 256
#define NHEAD 8
#define HEADD 32
#define MROWS (BATCH*SEQ)   /* 16384 */
#define ADIM 32
#define NSLOT 42
#define SLOT_SZ 65536

// ---------------- scratch (device globals; no allocation allowed) ------------
__device__ float g_x[MROWS*EMB];
__device__ float g_g[MROWS*EMB];     // swish(gate), fp32
__device__ float g_t[MROWS*EMB];
__device__ float g_z[MROWS*EMB];
__device__ __nv_bfloat16 g_xH[MROWS*EMB], g_xL[MROWS*EMB];
__device__ __nv_bfloat16 g_oH[MROWS*EMB], g_oL[MROWS*EMB];
__device__ __nv_bfloat16 g_zH[MROWS*EMB], g_zL[MROWS*EMB];
__device__ __nv_bfloat16 g_qH[MROWS*EMB], g_qL[MROWS*EMB];
__device__ __nv_bfloat16 g_kH[MROWS*EMB], g_kL[MROWS*EMB];
__device__ __nv_bfloat16 g_vH[MROWS*EMB], g_vL[MROWS*EMB];
__device__ __nv_bfloat16 g_aH[MROWS*ADIM], g_aL[MROWS*ADIM];
__device__ __nv_bfloat16 g_wH[NSLOT*SLOT_SZ], g_wL[NSLOT*SLOT_SZ];

__device__ __forceinline__ float gelu_tanh(float x){
    float x3 = x*x*x;
    return 0.5f*x*(1.f + tanhf(0.7978845608028654f*(x + 0.044715f*x3)));
}
__device__ __forceinline__ float swish_f(float x){
    return x / (1.f + expf(-x));
}
__device__ __forceinline__ uint32_t smem_u32(const void* p){
    uint32_t a;
    asm("{ .reg .u64 t; cvta.to.shared.u64 t, %1; cvt.u32.u64 %0, t; }" : "=r"(a) : "l"(p));
    return a;
}
__device__ __forceinline__ uint32_t pack2(float a, float b, uint32_t& lo){
    __nv_bfloat16 ha = __float2bfloat16(a), hb = __float2bfloat16(b);
    __nv_bfloat16 la = __float2bfloat16(a - __bfloat162float(ha));
    __nv_bfloat16 lb = __float2bfloat16(b - __bfloat162float(hb));
    lo = (uint32_t)__bfloat16_as_ushort(la) | ((uint32_t)__bfloat16_as_ushort(lb)<<16);
    return (uint32_t)__bfloat16_as_ushort(ha) | ((uint32_t)__bfloat16_as_ushort(hb)<<16);
}

#define LDSM4(r, addr) \
    asm volatile("ldmatrix.sync.aligned.m8n8.x4.shared.b16 {%0,%1,%2,%3}, [%4];" \
        : "=r"((r)[0]),"=r"((r)[1]),"=r"((r)[2]),"=r"((r)[3]) : "r"(addr))
#define LDSM4T(r, addr) \
    asm volatile("ldmatrix.sync.aligned.m8n8.x4.trans.shared.b16 {%0,%1,%2,%3}, [%4];" \
        : "=r"((r)[0]),"=r"((r)[1]),"=r"((r)[2]),"=r"((r)[3]) : "r"(addr))
#define MMA16816(c, a, b) \
    asm volatile("mma.sync.aligned.m16n8k16.row.col.f32.bf16.bf16.f32 " \
        "{%0,%1,%2,%3}, {%4,%5,%6,%7}, {%8,%9}, {%0,%1,%2,%3};" \
        : "+f"((c)[0]),"+f"((c)[1]),"+f"((c)[2]),"+f"((c)[3]) \
        : "r"((a)[0]),"r"((a)[1]),"r"((a)[2]),"r"((a)[3]), "r"((b)[0]),"r"((b)[1]))
#define CPA16(dst, src) \
    asm volatile("cp.async.cg.shared.global [%0],[%1],16;" :: "r"(dst),"l"(src))
#define CPA16Z(dst, src, sz) \
    asm volatile("cp.async.cg.shared.global [%0],[%1],16,%2;" :: "r"(dst),"l"(src),"r"(sz))
#define CPA_COMMIT() asm volatile("cp.async.commit_group;" ::: "memory")
#define CPA_WAIT1()  asm volatile("cp.async.wait_group 1;" ::: "memory")
#define CPA_WAIT0()  asm volatile("cp.async.wait_group 0;" ::: "memory")

// ---------------- conversion kernels -----------------------------------------
struct ConvW { const float* src[NSLOT]; int sz[NSLOT]; };
__global__ void conv_w(ConvW cw, __nv_bfloat16* wh, __nv_bfloat16* wl){
    const int slot = blockIdx.x;
    const int n = cw.sz[slot];
    const float* s = cw.src[slot];
    for (int i = blockIdx.y*blockDim.x + threadIdx.x; i < n; i += gridDim.y*blockDim.x){
        float v = s[i];
        __nv_bfloat16 h = __float2bfloat16(v);
        wh[slot*SLOT_SZ + i] = h;
        wl[slot*SLOT_SZ + i] = __float2bfloat16(v - __bfloat162float(h));
    }
}
__global__ void conv_a(const float* __restrict__ s, __nv_bfloat16* __restrict__ h,
                       __nv_bfloat16* __restrict__ l, int n){
    for (int i = blockIdx.x*blockDim.x + threadIdx.x; i < n; i += gridDim.x*blockDim.x){
        float v = s[i];
        __nv_bfloat16 hh = __float2bfloat16(v);
        h[i] = hh;
        l[i] = __float2bfloat16(v - __bfloat162float(hh));
    }
}

// ---------------- bf16x3 HGEMM, 128x64, cp.async, x4 ldmatrix ----------------
struct GemmP {
    const __nv_bfloat16 *AH[4], *AL[4];
    const __nv_bfloat16 *WH[4], *WL[4];
    float* C[4];
    __nv_bfloat16 *CH4[4], *CL4[4];
    int mode[4];
    __nv_bfloat16 *CH, *CL;
    const float* bias; const float* aux;
    int N; int K;
};

#define STG 29696
#define OFF_AL 10240
#define OFF_BH 20480
#define OFF_BL 25088
#define SMEM_TOT (3*STG)

template<int EPI>
__global__ __launch_bounds__(256,2)
void hgemm(GemmP p)
{
    extern __shared__ char smem[];
    const uint32_t sb = smem_u32(smem);
    const uint32_t sbEnd = sb + 3*STG;
    const int tid = threadIdx.x;
    const int lane = tid&31, warp = tid>>5;
    const int wm = warp&3, wn = warp>>2;
    const int bm0 = blockIdx.x*128;
    const int N = p.N, K = p.K;
    const int NT = (N>=64) ? (N>>6) : 1;
    const int mi = blockIdx.y / NT;
    const int bn0 = (blockIdx.y % NT)*64;
    const __nv_bfloat16* __restrict__ AH = p.AH[mi];
    const __nv_bfloat16* __restrict__ AL = p.AL[mi];
    const __nv_bfloat16* __restrict__ WH = p.WH[mi];
    const __nv_bfloat16* __restrict__ WL = p.WL[mi];
    float* __restrict__ C = p.C[mi];
    const int nc = K>>5;

    float acc[2][4][4];
    #pragma unroll
    for (int mt=0;mt<2;mt++)
        #pragma unroll
        for (int j=0;j<4;j++)
            #pragma unroll
            for (int e=0;e<4;e++) acc[mt][j][e]=0.f;

    const int ar0 = tid>>1, aq0 = (tid&1)*2;
    const int br = tid>>3, bq = tid&7;
    const int bcol = bn0 + bq*8;
    const int bvalid = (bcol < N) ? 16 : 0;
    const int bcolc = (bcol < N) ? bcol : 0;

    // strength-reduced producer state: pointers advance by constants
    const __nv_bfloat16* apH = AH + (size_t)(bm0+ar0)*K + aq0*8;
    const __nv_bfloat16* apL = AL + (size_t)(bm0+ar0)*K + aq0*8;
    const __nv_bfloat16* wpH = WH + (size_t)br*N + bcolc;
    const __nv_bfloat16* wpL = WL + (size_t)br*N + bcolc;
    const size_t wStep = (size_t)32*N;
    uint32_t isb = sb;
    const uint32_t aDst = (uint32_t)(ar0*80 + aq0*16);
    const uint32_t bDst = (uint32_t)(OFF_BH + br*144 + bq*16);

    auto issue = [&](){
        const uint32_t dh = isb + aDst;
        CPA16(dh,               apH);
        CPA16(dh + 16,          apH + 8);
        CPA16(dh + OFF_AL,      apL);
        CPA16(dh + OFF_AL + 16, apL + 8);
        const uint32_t dB = isb + bDst;
        CPA16Z(dB,                   wpH, bvalid);
        CPA16Z(dB + (OFF_BL-OFF_BH), wpL, bvalid);
        CPA_COMMIT();
        apH += 32; apL += 32; wpH += wStep; wpL += wStep;
        isb += STG; if (isb == sbEnd) isb = sb;
    };

    {
        const int npro = (nc < 2) ? nc : 2;
        for (int s=0; s<npro; s++) issue();
    }

    const uint32_t aro = (uint32_t)(wm*32 + (lane&15));
    const uint32_t bro = (uint32_t)(lane&15);
    const uint32_t bcol2 = (uint32_t)(wn*64 + ((lane>>4)&1)*16);  // bytes
    uint32_t csb = sb;

    for (int c=0; c<nc; c++){
        if (c == nc-1) CPA_WAIT0();
        else           CPA_WAIT1();
        __syncthreads();               // chunk c visible; slot (c-1)%3 free
        if (c+2 < nc) issue();

        const uint32_t sA  = csb;
        const uint32_t sAl = csb + OFF_AL;
        const uint32_t sB  = csb + OFF_BH;
        const uint32_t sBl = csb + OFF_BL;
        csb += STG; if (csb == sbEnd) csb = sb;

        #pragma unroll
        for (int s=0; s<2; s++){
            const uint32_t acol = (uint32_t)(s*16 + (lane>>4)*8)*2;
            uint32_t ah[2][4], al[2][4], bh[2][4], bl[2][4];
            #pragma unroll
            for (int mt=0; mt<2; mt++){
                const uint32_t ao = (aro + mt*16)*80 + acol;
                LDSM4(ah[mt], sA  + ao);
                LDSM4(al[mt], sAl + ao);
            }
            const uint32_t brow = (uint32_t)(s*16) + bro;
            #pragma unroll
            for (int jp=0; jp<2; jp++){
                const uint32_t bo = brow*144 + bcol2 + (uint32_t)(jp*32);
                LDSM4T(bh[jp], sB  + bo);
                LDSM4T(bl[jp], sBl + bo);
            }
            #pragma unroll
            for (int mt=0; mt<2; mt++)
                #pragma unroll
                for (int jp=0; jp<2; jp++){
                    MMA16816(acc[mt][2*jp+0], ah[mt], bh[jp]);
                    MMA16816(acc[mt][2*jp+1], ah[mt], bh[jp]+2);
                }
            #pragma unroll
            for (int mt=0; mt<2; mt++)
                #pragma unroll
                for (int jp=0; jp<2; jp++){
                    MMA16816(acc[mt][2*jp+0], ah[mt], bl[jp]);
                    MMA16816(acc[mt][2*jp+1], ah[mt], bl[jp]+2);
                }
            #pragma unroll
            for (int mt=0; mt<2; mt++)
                #pragma unroll
                for (int jp=0; jp<2; jp++){
                    MMA16816(acc[mt][2*jp+0], al[mt], bh[jp]);
                    MMA16816(acc[mt][2*jp+1], al[mt], bh[jp]+2);
                }
        }
    }

    const int g = lane>>2, tq = lane&3;

    if (EPI == 5){
        __syncthreads();
        float* l2g = (float*)smem;
        if (tid < 8){
            float lg = -3.4657359027997265f + (float)tid * (-0.39608410032853687f);
            l2g[tid] = log2f(1.f - expf(lg));
        }
        __syncthreads();
        const int mode = p.mode[mi];
        __nv_bfloat16* CH = p.CH4[mi];
        __nv_bfloat16* CL = p.CL4[mi];
        #pragma unroll
        for (int mt=0; mt<2; mt++){
            #pragma unroll
            for (int j=0; j<4; j++){
                const int col = bn0 + wn*32 + j*8 + tq*2;
                const float lg2 = l2g[col>>5];
                #pragma unroll
                for (int half=0; half<2; half++){
                    const int row = bm0 + wm*32 + mt*16 + g + half*8;
                    float v0 = acc[mt][j][2*half+0];
                    float v1 = acc[mt][j][2*half+1];
                    if (mode == 4){
                        *(float2*)(C + (size_t)row*N + col)
                            = make_float2(swish_f(v0), swish_f(v1));
                    } else {
                        if (mode == 1){
                            const float t = (float)((row & 255)>>3);
                            const float s = exp2f(t*lg2) * 0.17677669529663687f;
                            v0 *= s; v1 *= s;
                        } else if (mode == 2){
                            const float t = (float)((row & 255)>>3);
                            const float s = exp2f(-t*lg2);
                            v0 *= s; v1 *= s;
                        }
                        uint32_t lo, hi = pack2(v0, v1, lo);
                        *(uint32_t*)(CH + (size_t)row*N + col) = hi;
                        *(uint32_t*)(CL + (size_t)row*N + col) = lo;
                    }
                }
            }
        }
    } else {
        #pragma unroll
        for (int mt=0; mt<2; mt++){
            const int r0 = bm0 + wm*32 + mt*16 + g;
            #pragma unroll
            for (int j=0; j<4; j++){
                const int col = bn0 + wn*32 + j*8 + tq*2;
                if (col < N){
                    #pragma unroll
                    for (int half=0; half<2; half++){
                        const int row = r0 + half*8;
                        float v0 = acc[mt][j][2*half+0];
                        float v1 = acc[mt][j][2*half+1];
                        if (EPI==1){
                            if (p.bias){ v0 += p.bias[col]; v1 += p.bias[col+1]; }
                            v0 = gelu_tanh(v0); v1 = gelu_tanh(v1);
                            *(float2*)(C + (size_t)row*N + col) = make_float2(v0,v1);
                        } else if (EPI==2){
                            const float2 xa = *(const float2*)(p.aux + (size_t)row*N + col);
                            v0 = swish_f(v0)*xa.x; v1 = swish_f(v1)*xa.y;
                            uint32_t lo, hi = pack2(v0, v1, lo);
                            *(uint32_t*)(p.CH + (size_t)row*N + col) = hi;
                            *(uint32_t*)(p.CL + (size_t)row*N + col) = lo;
                        } else if (EPI==3){
                            v0 += p.bias[col]; v1 += p.bias[col+1];
                            *(float2*)(C + (size_t)row*N + col) = make_float2(v0,v1);
                        } else {
                            *(float2*)(C + (size_t)row*N + col) = make_float2(v0,v1);
                        }
                    }
                }
            }
        }
    }
}

// ---------------- tensor-core retention attention (x4 ldmatrix) --------------
#define QROW 80
#define AQ_SZ (128*QROW)
#define AKV_SZ (64*QROW)
#define ABUF (4*AKV_SZ)
#define ATT_SMEM (2*AQ_SZ + 3*ABUF)

__global__ __launch_bounds__(256,2)
void attn_tc(const __nv_bfloat16* __restrict__ qh, const __nv_bfloat16* __restrict__ ql,
             const __nv_bfloat16* __restrict__ kh, const __nv_bfloat16* __restrict__ kl,
             const __nv_bfloat16* __restrict__ vh, const __nv_bfloat16* __restrict__ vl,
             const float* __restrict__ gsw,
             const float* __restrict__ gns, const float* __restrict__ gnb,
             __nv_bfloat16* __restrict__ zh, __nv_bfloat16* __restrict__ zl)
{
    extern __shared__ char smem[];
    const uint32_t sb = smem_u32(smem);

    const int b = blockIdx.z, h = blockIdx.y, rt = blockIdx.x;
    const int tid = threadIdx.x;
    const int lane = tid&31, wid = tid>>5;

    #pragma unroll
    for (int i=0;i<2;i++){
        const int idx = tid + i*256;
        const int row = idx>>2, seg = idx&3;
        const size_t gb = (size_t)(b*SEQ + rt*128 + row)*EMB + h*HEADD + seg*8;
        *(uint4*)(smem + row*QROW + seg*16)         = *(const uint4*)(qh + gb);
        *(uint4*)(smem + AQ_SZ + row*QROW + seg*16) = *(const uint4*)(ql + gb);
    }

    const int rowbase = rt*128 + wid*16;
    const int nchunks = 2*(rt+1);

    // strength-reduced K/V producer
    const int krow = tid>>2, kseg = tid&3;
    const size_t kv0 = (size_t)(b*SEQ + krow)*EMB + h*HEADD + kseg*8;
    const __nv_bfloat16* kpH = kh + kv0;
    const __nv_bfloat16* kpL = kl + kv0;
    const __nv_bfloat16* vpH = vh + kv0;
    const __nv_bfloat16* vpL = vl + kv0;
    const size_t kvStep = (size_t)64*EMB;
    const uint32_t kvDst = (uint32_t)(krow*QROW + kseg*16);
    uint32_t ksb = sb + 2*AQ_SZ;
    const uint32_t ksbEnd = sb + 2*AQ_SZ + 3*ABUF;

    auto kv_issue = [&](){
        const uint32_t d = ksb + kvDst;
        CPA16(d,            kpH);
        CPA16(d + AKV_SZ,   kpL);
        CPA16(d + 2*AKV_SZ, vpH);
        CPA16(d + 3*AKV_SZ, vpL);
        CPA_COMMIT();
        kpH += kvStep; kpL += kvStep; vpH += kvStep; vpL += kvStep;
        ksb += ABUF; if (ksb == ksbEnd) ksb = sb + 2*AQ_SZ;
    };
    {
        const int npro = (nchunks < 2) ? nchunks : 2;
        for (int s=0; s<npro; s++) kv_issue();
    }
    __syncthreads();

    uint32_t qfh[2][4], qfl[2][4];
    {
        const uint32_t aro = (uint32_t)(wid*16 + (lane&15));
        #pragma unroll
        for (int kt=0; kt<2; kt++){
            const uint32_t ao = aro*QROW + (uint32_t)(kt*16 + (lane>>4)*8)*2;
            LDSM4(qfh[kt], sb + ao);
            LDSM4(qfl[kt], sb + AQ_SZ + ao);
        }
    }

    float oacc[4][4];
    #pragma unroll
    for (int jn=0;jn<4;jn++)
        #pragma unroll
        for (int e=0;e<4;e++) oacc[jn][e]=0.f;

    uint32_t csb = sb + 2*AQ_SZ;
    const uint32_t kAddrBase = (uint32_t)((lane&7))*QROW + (uint32_t)((lane>>3)&1)*16
                             + (uint32_t)(lane>>4)*8*QROW;   // + jp*16*QROW + kt*32
    const uint32_t vColBase = (uint32_t)((lane>>4)*8)*2;     // + jnp*32

    for (int mc=0; mc<nchunks; mc++){
        if (mc == nchunks-1) CPA_WAIT0();
        else                 CPA_WAIT1();
        __syncthreads();
        if (mc+2 < nchunks) kv_issue();

        const uint32_t kvb = csb;
        csb += ABUF; if (csb == ksbEnd) csb = sb + 2*AQ_SZ;

        const int mbase = mc*64;
        if (mbase > rowbase + 15) continue;

        const uint32_t kb  = kvb,             klb = kvb + AKV_SZ;
        const uint32_t vb  = kvb + 2*AKV_SZ,  vlb = kvb + 3*AKV_SZ;

        float sacc[8][4];
        #pragma unroll
        for (int j=0;j<8;j++)
            #pragma unroll
            for (int e=0;e<4;e++) sacc[j][e]=0.f;

        #pragma unroll
        for (int kt=0; kt<2; kt++){
            #pragma unroll
            for (int jp=0; jp<4; jp++){
                // x4 non-trans: tiles {j=2jp (k lo), j=2jp (k hi), j=2jp+1 (k lo), j=2jp+1 (k hi)}
                const uint32_t addr = kAddrBase + (uint32_t)(jp*16)*QROW + (uint32_t)(kt*32);
                uint32_t kfh[4], kfl[4];
                LDSM4(kfh, kb  + addr);
                LDSM4(kfl, klb + addr);
                MMA16816(sacc[2*jp+0], qfh[kt], kfh);
                MMA16816(sacc[2*jp+1], qfh[kt], kfh+2);
                MMA16816(sacc[2*jp+0], qfl[kt], kfh);
                MMA16816(sacc[2*jp+1], qfl[kt], kfh+2);
                MMA16816(sacc[2*jp+0], qfh[kt], kfl);
                MMA16816(sacc[2*jp+1], qfh[kt], kfl+2);
            }
        }

        if (mbase + 63 > rowbase){
            const int nr = rowbase + (lane>>2);
            const int mcb = mbase + (lane&3)*2;
            #pragma unroll
            for (int j=0;j<8;j++){
                const int m0 = mcb + j*8;
                if (m0   > nr)   sacc[j][0]=0.f;
                if (m0+1 > nr)   sacc[j][1]=0.f;
                if (m0   > nr+8) sacc[j][2]=0.f;
                if (m0+1 > nr+8) sacc[j][3]=0.f;
            }
        }

        #pragma unroll
        for (int kt2=0; kt2<4; kt2++){
            uint32_t ah[4], al[4];
            ah[0] = pack2(sacc[2*kt2][0],   sacc[2*kt2][1],   al[0]);
            ah[1] = pack2(sacc[2*kt2][2],   sacc[2*kt2][3],   al[1]);
            ah[2] = pack2(sacc[2*kt2+1][0], sacc[2*kt2+1][1], al[2]);
            ah[3] = pack2(sacc[2*kt2+1][2], sacc[2*kt2+1][3], al[3]);
            const uint32_t rowb = (uint32_t)(kt2*16 + (lane&15))*QROW;
            #pragma unroll
            for (int jnp=0; jnp<2; jnp++){
                const uint32_t addr = rowb + vColBase + (uint32_t)(jnp*32);
                uint32_t vfh[4], vfl[4];
                LDSM4T(vfh, vb  + addr);
                LDSM4T(vfl, vlb + addr);
                MMA16816(oacc[2*jnp+0], ah, vfh);
                MMA16816(oacc[2*jnp+1], ah, vfh+2);
                MMA16816(oacc[2*jnp+0], al, vfh);
                MMA16816(oacc[2*jnp+1], al, vfh+2);
                MMA16816(oacc[2*jnp+0], ah, vfl);
                MMA16816(oacc[2*jnp+1], ah, vfl+2);
            }
        }
    }

    const int gl = lane>>2, tq = lane&3;
    float sum0=0.f, sum1=0.f;
    #pragma unroll
    for (int jn=0;jn<4;jn++){
        sum0 += oacc[jn][0] + oacc[jn][1];
        sum1 += oacc[jn][2] + oacc[jn][3];
    }
    sum0 += __shfl_xor_sync(0xffffffffu, sum0, 1);
    sum0 += __shfl_xor_sync(0xffffffffu, sum0, 2);
    sum1 += __shfl_xor_sync(0xffffffffu, sum1, 1);
    sum1 += __shfl_xor_sync(0xffffffffu, sum1, 2);
    const float mu0 = sum0*(1.f/32.f), mu1 = sum1*(1.f/32.f);
    float v0=0.f, v1=0.f;
    #pragma unroll
    for (int jn=0;jn<4;jn++){
        float d0 = oacc[jn][0]-mu0, d1 = oacc[jn][1]-mu0;
        float d2 = oacc[jn][2]-mu1, d3 = oacc[jn][3]-mu1;
        v0 += d0*d0 + d1*d1;
        v1 += d2*d2 + d3*d3;
    }
    v0 += __shfl_xor_sync(0xffffffffu, v0, 1);
    v0 += __shfl_xor_sync(0xffffffffu, v0, 2);
    v1 += __shfl_xor_sync(0xffffffffu, v1, 1);
    v1 += __shfl_xor_sync(0xffffffffu, v1, 2);
    const float inv0 = rsqrtf(v0*(1.f/32.f) + 1e-5f);
    const float inv1 = rsqrtf(v1*(1.f/32.f) + 1e-5f);

    const int n0 = rowbase + gl;
    const size_t base0 = (size_t)(b*SEQ + n0)*EMB + h*HEADD;
    const size_t base1 = base0 + 8*EMB;
    #pragma unroll
    for (int jn=0;jn<4;jn++){
        const int c = jn*8 + tq*2;
        const float2 gs = *(const float2*)(gns + h*HEADD + c);
        const float2 gb2 = *(const float2*)(gnb + h*HEADD + c);
        float2 gg0 = *(const float2*)(gsw + base0 + c);
        float2 gg1 = *(const float2*)(gsw + base1 + c);
        float y0 = ((oacc[jn][0]-mu0)*inv0*gs.x + gb2.x) * gg0.x;
        float y1 = ((oacc[jn][1]-mu0)*inv0*gs.y + gb2.y) * gg0.y;
        float y2 = ((oacc[jn][2]-mu1)*inv1*gs.x + gb2.x) * gg1.x;
        float y3 = ((oacc[jn][3]-mu1)*inv1*gs.y + gb2.y) * gg1.y;
        uint32_t l01, h01 = pack2(y0, y1, l01);
        uint32_t l23, h23 = pack2(y2, y3, l23);
        *(uint32_t*)(zh + base0 + c) = h01;
        *(uint32_t*)(zl + base0 + c) = l01;
        *(uint32_t*)(zh + base1 + c) = h23;
        *(uint32_t*)(zl + base1 + c) = l23;
    }
}

// ---------------- rmsnorm (fused residual) + bf16 split out ------------------
__global__ __launch_bounds__(256)
void rmsnorm_kernel(const float* __restrict__ a, const float* __restrict__ b,
                    const float* __restrict__ scale, float* __restrict__ out,
                    __nv_bfloat16* __restrict__ outH, __nv_bfloat16* __restrict__ outL)
{
    const int row = blockIdx.x;
    const int tid = threadIdx.x;
    const size_t idx = (size_t)row*EMB + tid;
    float v = a[idx];
    if (b) v += b[idx];
    float sq = v*v;
    #pragma unroll
    for (int o=16;o;o>>=1) sq += __shfl_xor_sync(0xffffffffu, sq, o);
    __shared__ float ws[8];
    if ((tid & 31) == 0) ws[tid>>5] = sq;
    __syncthreads();
    float tot = 0.f;
    #pragma unroll
    for (int w=0; w<8; w++) tot += ws[w];
    float y = v * rsqrtf(tot*(1.f/256.f) + 1e-6f) * scale[tid];
    out[idx] = y;
    __nv_bfloat16 hh = __float2bfloat16(y);
    outH[idx] = hh;
    outL[idx] = __float2bfloat16(y - __bfloat162float(hh));
}

// ---------------- launcher ---------------------------------------------------
extern "C" void kernel_launch(void* const* d_in, const int* in_sizes, int n_in,
                              void* d_out, int out_size)
{
    (void)in_sizes; (void)n_in; (void)out_size;
    const float* action = (const float*)d_in[0];
    const float* obs    = (const float*)d_in[1];
    const float* w_enc  = (const float*)d_in[2];
    const float* ln0    = (const float*)d_in[3];
    const float* wq1    = (const float*)d_in[4];
    const float* wk1    = (const float*)d_in[5];
    const float* wv1    = (const float*)d_in[6];
    const float* wg1    = (const float*)d_in[7];
    const float* wo1    = (const float*)d_in[8];
    const float* gns1   = (const float*)d_in[9];
    const float* gnb1   = (const float*)d_in[10];
    const float* ln1    = (const float*)d_in[11];
    const float* wq2    = (const float*)d_in[12];
    const float* wk2    = (const float*)d_in[13];
    const float* wv2    = (const float*)d_in[14];
    const float* wg2    = (const float*)d_in[15];
    const float* wo2    = (const float*)d_in[16];
    const float* gns2   = (const float*)d_in[17];
    const float* gnb2   = (const float*)d_in[18];
    const float* ln2    = (const float*)d_in[19];
    const float* swg    = (const float*)d_in[20];
    const float* sw1    = (const float*)d_in[21];
    const float* sw2    = (const float*)d_in[22];
    const float* ln3    = (const float*)d_in[23];
    const float* hw1    = (const float*)d_in[24];
    const float* hb1    = (const float*)d_in[25];
    const float* hln    = (const float*)d_in[26];
    const float* hw2    = (const float*)d_in[27];
    const float* hb2    = (const float*)d_in[28];
    float* out = (float*)d_out;

    float *x,*gw,*tb,*zb;
    __nv_bfloat16 *xH,*xL,*oH,*oL,*zH,*zL,*qH,*qL,*kH,*kL,*vH,*vL,*aH,*aL,*wH,*wL;
    cudaGetSymbolAddress((void**)&x,  g_x);
    cudaGetSymbolAddress((void**)&gw, g_g);
    cudaGetSymbolAddress((void**)&tb, g_t);
    cudaGetSymbolAddress((void**)&zb, g_z);
    cudaGetSymbolAddress((void**)&xH, g_xH);
    cudaGetSymbolAddress((void**)&xL, g_xL);
    cudaGetSymbolAddress((void**)&oH, g_oH);
    cudaGetSymbolAddress((void**)&oL, g_oL);
    cudaGetSymbolAddress((void**)&zH, g_zH);
    cudaGetSymbolAddress((void**)&zL, g_zL);
    cudaGetSymbolAddress((void**)&qH, g_qH);
    cudaGetSymbolAddress((void**)&qL, g_qL);
    cudaGetSymbolAddress((void**)&kH, g_kH);
    cudaGetSymbolAddress((void**)&kL, g_kL);
    cudaGetSymbolAddress((void**)&vH, g_vH);
    cudaGetSymbolAddress((void**)&vL, g_vL);
    cudaGetSymbolAddress((void**)&aH, g_aH);
    cudaGetSymbolAddress((void**)&aL, g_aL);
    cudaGetSymbolAddress((void**)&wH, g_wH);
    cudaGetSymbolAddress((void**)&wL, g_wL);

    cudaFuncSetAttribute(hgemm<0>, cudaFuncAttributeMaxDynamicSharedMemorySize, SMEM_TOT);
    cudaFuncSetAttribute(hgemm<1>, cudaFuncAttributeMaxDynamicSharedMemorySize, SMEM_TOT);
    cudaFuncSetAttribute(hgemm<2>, cudaFuncAttributeMaxDynamicSharedMemorySize, SMEM_TOT);
    cudaFuncSetAttribute(hgemm<3>, cudaFuncAttributeMaxDynamicSharedMemorySize, SMEM_TOT);
    cudaFuncSetAttribute(hgemm<5>, cudaFuncAttributeMaxDynamicSharedMemorySize, SMEM_TOT);
    cudaFuncSetAttribute(attn_tc, cudaFuncAttributeMaxDynamicSharedMemorySize, ATT_SMEM);

    const float* wlist1[13] = {wq1,wk1,wv1,wg1,wo1,wq2,wk2,wv2,wg2,wo2,swg,sw1,sw2};
    ConvW cw{};
    for (int blk=0; blk<3; blk++)
        for (int j=0; j<13; j++){
            cw.src[blk*13+j] = wlist1[j] + (size_t)blk*EMB*EMB;
            cw.sz[blk*13+j] = EMB*EMB;
        }
    cw.src[39] = w_enc; cw.sz[39] = ADIM*EMB;
    cw.src[40] = hw1;   cw.sz[40] = EMB*EMB;
    cw.src[41] = hw2;   cw.sz[41] = EMB*ADIM;

    conv_w<<<dim3(NSLOT,32),256>>>(cw, wH, wL);
    conv_a<<<2048,256>>>(action, aH, aL, MROWS*ADIM);
    conv_a<<<4096,256>>>(obs, oH, oL, MROWS*EMB);

    auto WHs = [&](int slot){ return (const __nv_bfloat16*)(wH + (size_t)slot*SLOT_SZ); };
    auto WLs = [&](int slot){ return (const __nv_bfloat16*)(wL + (size_t)slot*SLOT_SZ); };

    auto mk1 = [&](const __nv_bfloat16* ah, const __nv_bfloat16* al, int slot,
                   float* c, const float* bias, const float* aux,
                   __nv_bfloat16* ch, __nv_bfloat16* cl, int N, int K){
        GemmP p{};
        for (int i=0;i<4;i++){ p.AH[i]=ah; p.AL[i]=al; p.WH[i]=WHs(slot); p.WL[i]=WLs(slot); p.C[i]=c; }
        p.bias=bias; p.aux=aux; p.CH=ch; p.CL=cl; p.N=N; p.K=K;
        return p;
    };

    const dim3 g1(MROWS/128, 4);
    const dim3 g4(MROWS/128, 16);
    const dim3 gHead(MROWS/128, 1);
    const dim3 gAttn(SEQ/128, NHEAD, BATCH);

    // encoder
    hgemm<1><<<g1,256,SMEM_TOT>>>(mk1(aH, aL, 39, tb, nullptr, nullptr, nullptr, nullptr, EMB, ADIM));
    rmsnorm_kernel<<<MROWS,256>>>(tb, nullptr, ln0, x, xH, xL);

    for (int blk=0; blk<3; blk++){
        const int s0 = blk*13;
        const size_t vOff = (size_t)blk*EMB;

        // retention 1: q/k/v/g projections with fused scale/split/swish epilogue
        {
            GemmP p{};
            const int slots[4] = {s0+0, s0+1, s0+2, s0+3};
            __nv_bfloat16* chs[4] = {qH, kH, vH, nullptr};
            __nv_bfloat16* cls[4] = {qL, kL, vL, nullptr};
            const int modes[4] = {1, 2, 3, 4};
            for (int i=0;i<4;i++){
                p.AH[i]=xH; p.AL[i]=xL;
                p.WH[i]=WHs(slots[i]); p.WL[i]=WLs(slots[i]);
                p.C[i]=gw; p.CH4[i]=chs[i]; p.CL4[i]=cls[i]; p.mode[i]=modes[i];
            }
            p.N=EMB; p.K=EMB;
            hgemm<5><<<g4,256,SMEM_TOT>>>(p);
        }
        attn_tc<<<gAttn,256,ATT_SMEM>>>(qH, qL, kH, kL, vH, vL, gw, gns1+vOff, gnb1+vOff, zH, zL);
        hgemm<0><<<g1,256,SMEM_TOT>>>(mk1(zH, zL, s0+4, tb, nullptr, nullptr, nullptr, nullptr, EMB, EMB));
        rmsnorm_kernel<<<MROWS,256>>>(x, tb, ln1+vOff, x, xH, xL);

        // retention 2: q/g from obs, k/v from x
        {
            GemmP p{};
            const int slots[4] = {s0+5, s0+6, s0+7, s0+8};
            const __nv_bfloat16* ahs[4] = {oH, xH, xH, oH};
            const __nv_bfloat16* als[4] = {oL, xL, xL, oL};
            __nv_bfloat16* chs[4] = {qH, kH, vH, nullptr};
            __nv_bfloat16* cls[4] = {qL, kL, vL, nullptr};
            const int modes[4] = {1, 2, 3, 4};
            for (int i=0;i<4;i++){
                p.AH[i]=ahs[i]; p.AL[i]=als[i];
                p.WH[i]=WHs(slots[i]); p.WL[i]=WLs(slots[i]);
                p.C[i]=gw; p.CH4[i]=chs[i]; p.CL4[i]=cls[i]; p.mode[i]=modes[i];
            }
            p.N=EMB; p.K=EMB;
            hgemm<5><<<g4,256,SMEM_TOT>>>(p);
        }
        attn_tc<<<gAttn,256,ATT_SMEM>>>(qH, qL, kH, kL, vH, vL, gw, gns2+vOff, gnb2+vOff, zH, zL);
        hgemm<0><<<g1,256,SMEM_TOT>>>(mk1(zH, zL, s0+9, tb, nullptr, nullptr, nullptr, nullptr, EMB, EMB));
        rmsnorm_kernel<<<MROWS,256>>>(obs, tb, ln2+vOff, x, xH, xL);

        // swiglu
        hgemm<0><<<g1,256,SMEM_TOT>>>(mk1(xH, xL, s0+11, tb, nullptr, nullptr, nullptr, nullptr, EMB, EMB));
        hgemm<2><<<g1,256,SMEM_TOT>>>(mk1(xH, xL, s0+10, nullptr, nullptr, tb, zH, zL, EMB, EMB));
        hgemm<0><<<g1,256,SMEM_TOT>>>(mk1(zH, zL, s0+12, tb, nullptr, nullptr, nullptr, nullptr, EMB, EMB));
        rmsnorm_kernel<<<MROWS,256>>>(x, tb, ln3+vOff, x, xH, xL);
    }

    // head
    hgemm<1><<<g1,256,SMEM_TOT>>>(mk1(xH, xL, 40, tb, hb1, nullptr, nullptr, nullptr, EMB, EMB));
    rmsnorm_kernel<<<MROWS,256>>>(tb, nullptr, hln, zb, zH, zL);
    hgemm<3><<<gHead,256,SMEM_TOT>>>(mk1(zH, zL, 41, out, hb2, nullptr, nullptr, nullptr, ADIM, EMB));
}

// round 15
// speedup vs baseline: 1.4579x; 1.0286x over previous
#include <cuda_runtime.h>
#include <cuda_bf16.h>
#include <math.h>
#include <stdint.h>

#define BATCH 64
#define SEQ 256
#define EMB 256
#define NHEAD 8
#define HEADD 32
#define MROWS (BATCH*SEQ)   /* 16384 */
#define ADIM 32
#define NSLOT 42
#define SLOT_SZ 65536

// ---------------- scratch (device globals; no allocation allowed) ------------
__device__ float g_x[MROWS*EMB];
__device__ float g_g[MROWS*EMB];     // swish(gate), fp32
__device__ float g_t[MROWS*EMB];
__device__ float g_z[MROWS*EMB];
__device__ __nv_bfloat16 g_xH[MROWS*EMB], g_xL[MROWS*EMB];
__device__ __nv_bfloat16 g_oH[MROWS*EMB], g_oL[MROWS*EMB];
__device__ __nv_bfloat16 g_zH[MROWS*EMB], g_zL[MROWS*EMB];
__device__ __nv_bfloat16 g_qH[MROWS*EMB], g_qL[MROWS*EMB];
__device__ __nv_bfloat16 g_kH[MROWS*EMB], g_kL[MROWS*EMB];
__device__ __nv_bfloat16 g_vH[MROWS*EMB], g_vL[MROWS*EMB];
__device__ __nv_bfloat16 g_aH[MROWS*ADIM], g_aL[MROWS*ADIM];
__device__ __nv_bfloat16 g_wH[NSLOT*SLOT_SZ], g_wL[NSLOT*SLOT_SZ];

__device__ __forceinline__ float gelu_tanh(float x){
    float x3 = x*x*x;
    return 0.5f*x*(1.f + tanhf(0.7978845608028654f*(x + 0.044715f*x3)));
}
__device__ __forceinline__ float swish_f(float x){
    return x / (1.f + expf(-x));
}
__device__ __forceinline__ uint32_t smem_u32(const void* p){
    uint32_t a;
    asm("{ .reg .u64 t; cvta.to.shared.u64 t, %1; cvt.u32.u64 %0, t; }" : "=r"(a) : "l"(p));
    return a;
}
__device__ __forceinline__ uint32_t pack2(float a, float b, uint32_t& lo){
    __nv_bfloat16 ha = __float2bfloat16(a), hb = __float2bfloat16(b);
    __nv_bfloat16 la = __float2bfloat16(a - __bfloat162float(ha));
    __nv_bfloat16 lb = __float2bfloat16(b - __bfloat162float(hb));
    lo = (uint32_t)__bfloat16_as_ushort(la) | ((uint32_t)__bfloat16_as_ushort(lb)<<16);
    return (uint32_t)__bfloat16_as_ushort(ha) | ((uint32_t)__bfloat16_as_ushort(hb)<<16);
}

#define LDSM4(r, addr) \
    asm volatile("ldmatrix.sync.aligned.m8n8.x4.shared.b16 {%0,%1,%2,%3}, [%4];" \
        : "=r"((r)[0]),"=r"((r)[1]),"=r"((r)[2]),"=r"((r)[3]) : "r"(addr))
#define LDSM4T(r, addr) \
    asm volatile("ldmatrix.sync.aligned.m8n8.x4.trans.shared.b16 {%0,%1,%2,%3}, [%4];" \
        : "=r"((r)[0]),"=r"((r)[1]),"=r"((r)[2]),"=r"((r)[3]) : "r"(addr))
#define MMA16816(c, a, b) \
    asm volatile("mma.sync.aligned.m16n8k16.row.col.f32.bf16.bf16.f32 " \
        "{%0,%1,%2,%3}, {%4,%5,%6,%7}, {%8,%9}, {%0,%1,%2,%3};" \
        : "+f"((c)[0]),"+f"((c)[1]),"+f"((c)[2]),"+f"((c)[3]) \
        : "r"((a)[0]),"r"((a)[1]),"r"((a)[2]),"r"((a)[3]), "r"((b)[0]),"r"((b)[1]))
#define CPA16(dst, src) \
    asm volatile("cp.async.cg.shared.global [%0],[%1],16;" :: "r"(dst),"l"(src))
#define CPA16Z(dst, src, sz) \
    asm volatile("cp.async.cg.shared.global [%0],[%1],16,%2;" :: "r"(dst),"l"(src),"r"(sz))
#define CPA_COMMIT() asm volatile("cp.async.commit_group;" ::: "memory")
#define CPA_WAIT1()  asm volatile("cp.async.wait_group 1;" ::: "memory")
#define CPA_WAIT0()  asm volatile("cp.async.wait_group 0;" ::: "memory")

// ---------------- conversion kernels -----------------------------------------
struct ConvW { const float* src[NSLOT]; int sz[NSLOT]; };
__global__ void conv_w(ConvW cw, __nv_bfloat16* wh, __nv_bfloat16* wl){
    const int slot = blockIdx.x;
    const int n = cw.sz[slot];
    const float* s = cw.src[slot];
    for (int i = blockIdx.y*blockDim.x + threadIdx.x; i < n; i += gridDim.y*blockDim.x){
        float v = s[i];
        __nv_bfloat16 h = __float2bfloat16(v);
        wh[slot*SLOT_SZ + i] = h;
        wl[slot*SLOT_SZ + i] = __float2bfloat16(v - __bfloat162float(h));
    }
}
__global__ void conv_a(const float* __restrict__ s, __nv_bfloat16* __restrict__ h,
                       __nv_bfloat16* __restrict__ l, int n){
    for (int i = blockIdx.x*blockDim.x + threadIdx.x; i < n; i += gridDim.x*blockDim.x){
        float v = s[i];
        __nv_bfloat16 hh = __float2bfloat16(v);
        h[i] = hh;
        l[i] = __float2bfloat16(v - __bfloat162float(hh));
    }
}

// ---------------- bf16x3 HGEMM, 128x64, BK=16, 3-stage, occ 3 ----------------
struct GemmP {
    const __nv_bfloat16 *AH[4], *AL[4];
    const __nv_bfloat16 *WH[4], *WL[4];
    float* C[4];
    __nv_bfloat16 *CH4[4], *CL4[4];
    int mode[4];
    __nv_bfloat16 *CH, *CL;
    const float* bias; const float* aux;
    int N; int K;
};

#define APITCH 48
#define OFF_AL 6144                 /* 128*48 */
#define OFF_BH 12288
#define B_SZ   2304                 /* 16*144 */
#define OFF_BL (OFF_BH + B_SZ)
#define STG    (OFF_BH + 2*B_SZ)    /* 16896 */
#define SMEM_TOT (3*STG)            /* 50688 */

template<int EPI>
__global__ __launch_bounds__(256,3)
void hgemm(GemmP p)
{
    extern __shared__ char smem[];
    const uint32_t sb = smem_u32(smem);
    const uint32_t sbEnd = sb + 3*STG;
    const int tid = threadIdx.x;
    const int lane = tid&31, warp = tid>>5;
    const int wm = warp&3, wn = warp>>2;
    const int bm0 = blockIdx.x*128;
    const int N = p.N, K = p.K;
    const int NT = (N>=64) ? (N>>6) : 1;
    const int mi = blockIdx.y / NT;
    const int bn0 = (blockIdx.y % NT)*64;
    const __nv_bfloat16* __restrict__ AH = p.AH[mi];
    const __nv_bfloat16* __restrict__ AL = p.AL[mi];
    const __nv_bfloat16* __restrict__ WH = p.WH[mi];
    const __nv_bfloat16* __restrict__ WL = p.WL[mi];
    float* __restrict__ C = p.C[mi];
    const int nc = K>>4;

    float acc[2][4][4];
    #pragma unroll
    for (int mt=0;mt<2;mt++)
        #pragma unroll
        for (int j=0;j<4;j++)
            #pragma unroll
            for (int e=0;e<4;e++) acc[mt][j][e]=0.f;

    // producer mapping: A: 2 threads/row (16B seg each); B: 128 thr hi + 128 thr lo
    const int ar0 = tid>>1, aseg = tid&1;
    const int brh = (tid&127)>>3, bq = tid&7;
    const int half = tid>>7;
    const int bcol = bn0 + bq*8;
    const int bvalid = (bcol < N) ? 16 : 0;
    const int bcolc = (bcol < N) ? bcol : 0;

    const __nv_bfloat16* apH = AH + (size_t)(bm0+ar0)*K + aseg*8;
    const __nv_bfloat16* apL = AL + (size_t)(bm0+ar0)*K + aseg*8;
    const __nv_bfloat16* wp  = (half ? WL : WH) + (size_t)brh*N + bcolc;
    const size_t wStep = (size_t)16*N;
    uint32_t isb = sb;
    const uint32_t aDst = (uint32_t)(ar0*APITCH + aseg*16);
    const uint32_t bDst = (uint32_t)(OFF_BH + half*B_SZ + brh*144 + bq*16);

    auto issue = [&](){
        const uint32_t dh = isb + aDst;
        CPA16(dh,          apH);
        CPA16(dh + OFF_AL, apL);
        CPA16Z(isb + bDst, wp, bvalid);
        CPA_COMMIT();
        apH += 16; apL += 16; wp += wStep;
        isb += STG; if (isb == sbEnd) isb = sb;
    };

    {
        const int npro = (nc < 2) ? nc : 2;
        for (int s=0; s<npro; s++) issue();
    }

    const uint32_t aro = (uint32_t)(wm*32 + (lane&15));
    const uint32_t acolo = (uint32_t)((lane>>4)*16);
    const uint32_t bro = (uint32_t)(lane&15);
    const uint32_t bcol2 = (uint32_t)(wn*64 + ((lane>>4)&1)*16);
    uint32_t csb = sb;

    for (int c=0; c<nc; c++){
        if (c == nc-1) CPA_WAIT0();
        else           CPA_WAIT1();
        __syncthreads();               // chunk c visible; slot (c-1)%3 free
        if (c+2 < nc) issue();

        const uint32_t sA  = csb;
        const uint32_t sAl = csb + OFF_AL;
        const uint32_t sB  = csb + OFF_BH;
        const uint32_t sBl = csb + OFF_BL;
        csb += STG; if (csb == sbEnd) csb = sb;

        uint32_t ah[2][4], al[2][4], bh[2][4], bl[2][4];
        #pragma unroll
        for (int mt=0; mt<2; mt++){
            const uint32_t ao = (aro + mt*16)*APITCH + acolo;
            LDSM4(ah[mt], sA  + ao);
            LDSM4(al[mt], sAl + ao);
        }
        #pragma unroll
        for (int jp=0; jp<2; jp++){
            const uint32_t bo = bro*144 + bcol2 + (uint32_t)(jp*32);
            LDSM4T(bh[jp], sB  + bo);
            LDSM4T(bl[jp], sBl + bo);
        }
        #pragma unroll
        for (int mt=0; mt<2; mt++)
            #pragma unroll
            for (int jp=0; jp<2; jp++){
                MMA16816(acc[mt][2*jp+0], ah[mt], bh[jp]);
                MMA16816(acc[mt][2*jp+1], ah[mt], bh[jp]+2);
            }
        #pragma unroll
        for (int mt=0; mt<2; mt++)
            #pragma unroll
            for (int jp=0; jp<2; jp++){
                MMA16816(acc[mt][2*jp+0], ah[mt], bl[jp]);
                MMA16816(acc[mt][2*jp+1], ah[mt], bl[jp]+2);
            }
        #pragma unroll
        for (int mt=0; mt<2; mt++)
            #pragma unroll
            for (int jp=0; jp<2; jp++){
                MMA16816(acc[mt][2*jp+0], al[mt], bh[jp]);
                MMA16816(acc[mt][2*jp+1], al[mt], bh[jp]+2);
            }
    }

    const int g = lane>>2, tq = lane&3;

    if (EPI == 5){
        __syncthreads();
        float* l2g = (float*)smem;
        if (tid < 8){
            float lg = -3.4657359027997265f + (float)tid * (-0.39608410032853687f);
            l2g[tid] = log2f(1.f - expf(lg));
        }
        __syncthreads();
        const int mode = p.mode[mi];
        __nv_bfloat16* CH = p.CH4[mi];
        __nv_bfloat16* CL = p.CL4[mi];
        #pragma unroll
        for (int mt=0; mt<2; mt++){
            #pragma unroll
            for (int j=0; j<4; j++){
                const int col = bn0 + wn*32 + j*8 + tq*2;
                const float lg2 = l2g[col>>5];
                #pragma unroll
                for (int half2=0; half2<2; half2++){
                    const int row = bm0 + wm*32 + mt*16 + g + half2*8;
                    float v0 = acc[mt][j][2*half2+0];
                    float v1 = acc[mt][j][2*half2+1];
                    if (mode == 4){
                        *(float2*)(C + (size_t)row*N + col)
                            = make_float2(swish_f(v0), swish_f(v1));
                    } else {
                        if (mode == 1){
                            const float t = (float)((row & 255)>>3);
                            const float s = exp2f(t*lg2) * 0.17677669529663687f;
                            v0 *= s; v1 *= s;
                        } else if (mode == 2){
                            const float t = (float)((row & 255)>>3);
                            const float s = exp2f(-t*lg2);
                            v0 *= s; v1 *= s;
                        }
                        uint32_t lo, hi = pack2(v0, v1, lo);
                        *(uint32_t*)(CH + (size_t)row*N + col) = hi;
                        *(uint32_t*)(CL + (size_t)row*N + col) = lo;
                    }
                }
            }
        }
    } else {
        #pragma unroll
        for (int mt=0; mt<2; mt++){
            const int r0 = bm0 + wm*32 + mt*16 + g;
            #pragma unroll
            for (int j=0; j<4; j++){
                const int col = bn0 + wn*32 + j*8 + tq*2;
                if (col < N){
                    #pragma unroll
                    for (int half2=0; half2<2; half2++){
                        const int row = r0 + half2*8;
                        float v0 = acc[mt][j][2*half2+0];
                        float v1 = acc[mt][j][2*half2+1];
                        if (EPI==1){
                            if (p.bias){ v0 += p.bias[col]; v1 += p.bias[col+1]; }
                            v0 = gelu_tanh(v0); v1 = gelu_tanh(v1);
                            *(float2*)(C + (size_t)row*N + col) = make_float2(v0,v1);
                        } else if (EPI==2){
                            const float2 xa = *(const float2*)(p.aux + (size_t)row*N + col);
                            v0 = swish_f(v0)*xa.x; v1 = swish_f(v1)*xa.y;
                            uint32_t lo, hi = pack2(v0, v1, lo);
                            *(uint32_t*)(p.CH + (size_t)row*N + col) = hi;
                            *(uint32_t*)(p.CL + (size_t)row*N + col) = lo;
                        } else if (EPI==3){
                            v0 += p.bias[col]; v1 += p.bias[col+1];
                            *(float2*)(C + (size_t)row*N + col) = make_float2(v0,v1);
                        } else {
                            *(float2*)(C + (size_t)row*N + col) = make_float2(v0,v1);
                        }
                    }
                }
            }
        }
    }
}

// ---------------- tensor-core retention attention (x4 ldmatrix) --------------
#define QROW 80
#define AQ_SZ (128*QROW)
#define AKV_SZ (64*QROW)
#define ABUF (4*AKV_SZ)
#define ATT_SMEM (2*AQ_SZ + 3*ABUF)

__global__ __launch_bounds__(256,2)
void attn_tc(const __nv_bfloat16* __restrict__ qh, const __nv_bfloat16* __restrict__ ql,
             const __nv_bfloat16* __restrict__ kh, const __nv_bfloat16* __restrict__ kl,
             const __nv_bfloat16* __restrict__ vh, const __nv_bfloat16* __restrict__ vl,
             const float* __restrict__ gsw,
             const float* __restrict__ gns, const float* __restrict__ gnb,
             __nv_bfloat16* __restrict__ zh, __nv_bfloat16* __restrict__ zl)
{
    extern __shared__ char smem[];
    const uint32_t sb = smem_u32(smem);

    const int b = blockIdx.z, h = blockIdx.y;
    const int rt = gridDim.x - 1 - blockIdx.x;   // heavy tiles first
    const int tid = threadIdx.x;
    const int lane = tid&31, wid = tid>>5;

    #pragma unroll
    for (int i=0;i<2;i++){
        const int idx = tid + i*256;
        const int row = idx>>2, seg = idx&3;
        const size_t gb = (size_t)(b*SEQ + rt*128 + row)*EMB + h*HEADD + seg*8;
        *(uint4*)(smem + row*QROW + seg*16)         = *(const uint4*)(qh + gb);
        *(uint4*)(smem + AQ_SZ + row*QROW + seg*16) = *(const uint4*)(ql + gb);
    }

    const int rowbase = rt*128 + wid*16;
    const int nchunks = 2*(rt+1);

    const int krow = tid>>2, kseg = tid&3;
    const size_t kv0 = (size_t)(b*SEQ + krow)*EMB + h*HEADD + kseg*8;
    const __nv_bfloat16* kpH = kh + kv0;
    const __nv_bfloat16* kpL = kl + kv0;
    const __nv_bfloat16* vpH = vh + kv0;
    const __nv_bfloat16* vpL = vl + kv0;
    const size_t kvStep = (size_t)64*EMB;
    const uint32_t kvDst = (uint32_t)(krow*QROW + kseg*16);
    uint32_t ksb = sb + 2*AQ_SZ;
    const uint32_t ksbEnd = sb + 2*AQ_SZ + 3*ABUF;

    auto kv_issue = [&](){
        const uint32_t d = ksb + kvDst;
        CPA16(d,            kpH);
        CPA16(d + AKV_SZ,   kpL);
        CPA16(d + 2*AKV_SZ, vpH);
        CPA16(d + 3*AKV_SZ, vpL);
        CPA_COMMIT();
        kpH += kvStep; kpL += kvStep; vpH += kvStep; vpL += kvStep;
        ksb += ABUF; if (ksb == ksbEnd) ksb = sb + 2*AQ_SZ;
    };
    {
        const int npro = (nchunks < 2) ? nchunks : 2;
        for (int s=0; s<npro; s++) kv_issue();
    }
    __syncthreads();

    uint32_t qfh[2][4], qfl[2][4];
    {
        const uint32_t aro = (uint32_t)(wid*16 + (lane&15));
        #pragma unroll
        for (int kt=0; kt<2; kt++){
            const uint32_t ao = aro*QROW + (uint32_t)(kt*16 + (lane>>4)*8)*2;
            LDSM4(qfh[kt], sb + ao);
            LDSM4(qfl[kt], sb + AQ_SZ + ao);
        }
    }

    float oacc[4][4];
    #pragma unroll
    for (int jn=0;jn<4;jn++)
        #pragma unroll
        for (int e=0;e<4;e++) oacc[jn][e]=0.f;

    uint32_t csb = sb + 2*AQ_SZ;
    const uint32_t kAddrBase = (uint32_t)((lane&7))*QROW + (uint32_t)((lane>>3)&1)*16
                             + (uint32_t)(lane>>4)*8*QROW;
    const uint32_t vColBase = (uint32_t)((lane>>4)*8)*2;

    for (int mc=0; mc<nchunks; mc++){
        if (mc == nchunks-1) CPA_WAIT0();
        else                 CPA_WAIT1();
        __syncthreads();
        if (mc+2 < nchunks) kv_issue();

        const uint32_t kvb = csb;
        csb += ABUF; if (csb == ksbEnd) csb = sb + 2*AQ_SZ;

        const int mbase = mc*64;
        if (mbase > rowbase + 15) continue;

        const uint32_t kb  = kvb,             klb = kvb + AKV_SZ;
        const uint32_t vb  = kvb + 2*AKV_SZ,  vlb = kvb + 3*AKV_SZ;

        float sacc[8][4];
        #pragma unroll
        for (int j=0;j<8;j++)
            #pragma unroll
            for (int e=0;e<4;e++) sacc[j][e]=0.f;

        #pragma unroll
        for (int kt=0; kt<2; kt++){
            #pragma unroll
            for (int jp=0; jp<4; jp++){
                const uint32_t addr = kAddrBase + (uint32_t)(jp*16)*QROW + (uint32_t)(kt*32);
                uint32_t kfh[4], kfl[4];
                LDSM4(kfh, kb  + addr);
                LDSM4(kfl, klb + addr);
                MMA16816(sacc[2*jp+0], qfh[kt], kfh);
                MMA16816(sacc[2*jp+1], qfh[kt], kfh+2);
                MMA16816(sacc[2*jp+0], qfl[kt], kfh);
                MMA16816(sacc[2*jp+1], qfl[kt], kfh+2);
                MMA16816(sacc[2*jp+0], qfh[kt], kfl);
                MMA16816(sacc[2*jp+1], qfh[kt], kfl+2);
            }
        }

        if (mbase + 63 > rowbase){
            const int nr = rowbase + (lane>>2);
            const int mcb = mbase + (lane&3)*2;
            #pragma unroll
            for (int j=0;j<8;j++){
                const int m0 = mcb + j*8;
                if (m0   > nr)   sacc[j][0]=0.f;
                if (m0+1 > nr)   sacc[j][1]=0.f;
                if (m0   > nr+8) sacc[j][2]=0.f;
                if (m0+1 > nr+8) sacc[j][3]=0.f;
            }
        }

        #pragma unroll
        for (int kt2=0; kt2<4; kt2++){
            uint32_t ah[4], al[4];
            ah[0] = pack2(sacc[2*kt2][0],   sacc[2*kt2][1],   al[0]);
            ah[1] = pack2(sacc[2*kt2][2],   sacc[2*kt2][3],   al[1]);
            ah[2] = pack2(sacc[2*kt2+1][0], sacc[2*kt2+1][1], al[2]);
            ah[3] = pack2(sacc[2*kt2+1][2], sacc[2*kt2+1][3], al[3]);
            const uint32_t rowb = (uint32_t)(kt2*16 + (lane&15))*QROW;
            #pragma unroll
            for (int jnp=0; jnp<2; jnp++){
                const uint32_t addr = rowb + vColBase + (uint32_t)(jnp*32);
                uint32_t vfh[4], vfl[4];
                LDSM4T(vfh, vb  + addr);
                LDSM4T(vfl, vlb + addr);
                MMA16816(oacc[2*jnp+0], ah, vfh);
                MMA16816(oacc[2*jnp+1], ah, vfh+2);
                MMA16816(oacc[2*jnp+0], al, vfh);
                MMA16816(oacc[2*jnp+1], al, vfh+2);
                MMA16816(oacc[2*jnp+0], ah, vfl);
                MMA16816(oacc[2*jnp+1], ah, vfl+2);
            }
        }
    }

    const int gl = lane>>2, tq = lane&3;
    float sum0=0.f, sum1=0.f;
    #pragma unroll
    for (int jn=0;jn<4;jn++){
        sum0 += oacc[jn][0] + oacc[jn][1];
        sum1 += oacc[jn][2] + oacc[jn][3];
    }
    sum0 += __shfl_xor_sync(0xffffffffu, sum0, 1);
    sum0 += __shfl_xor_sync(0xffffffffu, sum0, 2);
    sum1 += __shfl_xor_sync(0xffffffffu, sum1, 1);
    sum1 += __shfl_xor_sync(0xffffffffu, sum1, 2);
    const float mu0 = sum0*(1.f/32.f), mu1 = sum1*(1.f/32.f);
    float v0=0.f, v1=0.f;
    #pragma unroll
    for (int jn=0;jn<4;jn++){
        float d0 = oacc[jn][0]-mu0, d1 = oacc[jn][1]-mu0;
        float d2 = oacc[jn][2]-mu1, d3 = oacc[jn][3]-mu1;
        v0 += d0*d0 + d1*d1;
        v1 += d2*d2 + d3*d3;
    }
    v0 += __shfl_xor_sync(0xffffffffu, v0, 1);
    v0 += __shfl_xor_sync(0xffffffffu, v0, 2);
    v1 += __shfl_xor_sync(0xffffffffu, v1, 1);
    v1 += __shfl_xor_sync(0xffffffffu, v1, 2);
    const float inv0 = rsqrtf(v0*(1.f/32.f) + 1e-5f);
    const float inv1 = rsqrtf(v1*(1.f/32.f) + 1e-5f);

    const int n0 = rowbase + gl;
    const size_t base0 = (size_t)(b*SEQ + n0)*EMB + h*HEADD;
    const size_t base1 = base0 + 8*EMB;
    #pragma unroll
    for (int jn=0;jn<4;jn++){
        const int c = jn*8 + tq*2;
        const float2 gs = *(const float2*)(gns + h*HEADD + c);
        const float2 gb2 = *(const float2*)(gnb + h*HEADD + c);
        float2 gg0 = *(const float2*)(gsw + base0 + c);
        float2 gg1 = *(const float2*)(gsw + base1 + c);
        float y0 = ((oacc[jn][0]-mu0)*inv0*gs.x + gb2.x) * gg0.x;
        float y1 = ((oacc[jn][1]-mu0)*inv0*gs.y + gb2.y) * gg0.y;
        float y2 = ((oacc[jn][2]-mu1)*inv1*gs.x + gb2.x) * gg1.x;
        float y3 = ((oacc[jn][3]-mu1)*inv1*gs.y + gb2.y) * gg1.y;
        uint32_t l01, h01 = pack2(y0, y1, l01);
        uint32_t l23, h23 = pack2(y2, y3, l23);
        *(uint32_t*)(zh + base0 + c) = h01;
        *(uint32_t*)(zl + base0 + c) = l01;
        *(uint32_t*)(zh + base1 + c) = h23;
        *(uint32_t*)(zl + base1 + c) = l23;
    }
}

// ---------------- rmsnorm (fused residual) + bf16 split out ------------------
__global__ __launch_bounds__(256)
void rmsnorm_kernel(const float* __restrict__ a, const float* __restrict__ b,
                    const float* __restrict__ scale, float* __restrict__ out,
                    __nv_bfloat16* __restrict__ outH, __nv_bfloat16* __restrict__ outL)
{
    const int row = blockIdx.x;
    const int tid = threadIdx.x;
    const size_t idx = (size_t)row*EMB + tid;
    float v = a[idx];
    if (b) v += b[idx];
    float sq = v*v;
    #pragma unroll
    for (int o=16;o;o>>=1) sq += __shfl_xor_sync(0xffffffffu, sq, o);
    __shared__ float ws[8];
    if ((tid & 31) == 0) ws[tid>>5] = sq;
    __syncthreads();
    float tot = 0.f;
    #pragma unroll
    for (int w=0; w<8; w++) tot += ws[w];
    float y = v * rsqrtf(tot*(1.f/256.f) + 1e-6f) * scale[tid];
    if (out) out[idx] = y;
    __nv_bfloat16 hh = __float2bfloat16(y);
    outH[idx] = hh;
    outL[idx] = __float2bfloat16(y - __bfloat162float(hh));
}

// ---------------- launcher ---------------------------------------------------
extern "C" void kernel_launch(void* const* d_in, const int* in_sizes, int n_in,
                              void* d_out, int out_size)
{
    (void)in_sizes; (void)n_in; (void)out_size;
    const float* action = (const float*)d_in[0];
    const float* obs    = (const float*)d_in[1];
    const float* w_enc  = (const float*)d_in[2];
    const float* ln0    = (const float*)d_in[3];
    const float* wq1    = (const float*)d_in[4];
    const float* wk1    = (const float*)d_in[5];
    const float* wv1    = (const float*)d_in[6];
    const float* wg1    = (const float*)d_in[7];
    const float* wo1    = (const float*)d_in[8];
    const float* gns1   = (const float*)d_in[9];
    const float* gnb1   = (const float*)d_in[10];
    const float* ln1    = (const float*)d_in[11];
    const float* wq2    = (const float*)d_in[12];
    const float* wk2    = (const float*)d_in[13];
    const float* wv2    = (const float*)d_in[14];
    const float* wg2    = (const float*)d_in[15];
    const float* wo2    = (const float*)d_in[16];
    const float* gns2   = (const float*)d_in[17];
    const float* gnb2   = (const float*)d_in[18];
    const float* ln2    = (const float*)d_in[19];
    const float* swg    = (const float*)d_in[20];
    const float* sw1    = (const float*)d_in[21];
    const float* sw2    = (const float*)d_in[22];
    const float* ln3    = (const float*)d_in[23];
    const float* hw1    = (const float*)d_in[24];
    const float* hb1    = (const float*)d_in[25];
    const float* hln    = (const float*)d_in[26];
    const float* hw2    = (const float*)d_in[27];
    const float* hb2    = (const float*)d_in[28];
    float* out = (float*)d_out;

    float *x,*gw,*tb,*zb;
    __nv_bfloat16 *xH,*xL,*oH,*oL,*zH,*zL,*qH,*qL,*kH,*kL,*vH,*vL,*aH,*aL,*wH,*wL;
    cudaGetSymbolAddress((void**)&x,  g_x);
    cudaGetSymbolAddress((void**)&gw, g_g);
    cudaGetSymbolAddress((void**)&tb, g_t);
    cudaGetSymbolAddress((void**)&zb, g_z);
    cudaGetSymbolAddress((void**)&xH, g_xH);
    cudaGetSymbolAddress((void**)&xL, g_xL);
    cudaGetSymbolAddress((void**)&oH, g_oH);
    cudaGetSymbolAddress((void**)&oL, g_oL);
    cudaGetSymbolAddress((void**)&zH, g_zH);
    cudaGetSymbolAddress((void**)&zL, g_zL);
    cudaGetSymbolAddress((void**)&qH, g_qH);
    cudaGetSymbolAddress((void**)&qL, g_qL);
    cudaGetSymbolAddress((void**)&kH, g_kH);
    cudaGetSymbolAddress((void**)&kL, g_kL);
    cudaGetSymbolAddress((void**)&vH, g_vH);
    cudaGetSymbolAddress((void**)&vL, g_vL);
    cudaGetSymbolAddress((void**)&aH, g_aH);
    cudaGetSymbolAddress((void**)&aL, g_aL);
    cudaGetSymbolAddress((void**)&wH, g_wH);
    cudaGetSymbolAddress((void**)&wL, g_wL);

    cudaFuncSetAttribute(hgemm<0>, cudaFuncAttributeMaxDynamicSharedMemorySize, SMEM_TOT);
    cudaFuncSetAttribute(hgemm<1>, cudaFuncAttributeMaxDynamicSharedMemorySize, SMEM_TOT);
    cudaFuncSetAttribute(hgemm<2>, cudaFuncAttributeMaxDynamicSharedMemorySize, SMEM_TOT);
    cudaFuncSetAttribute(hgemm<3>, cudaFuncAttributeMaxDynamicSharedMemorySize, SMEM_TOT);
    cudaFuncSetAttribute(hgemm<5>, cudaFuncAttributeMaxDynamicSharedMemorySize, SMEM_TOT);
    cudaFuncSetAttribute(attn_tc, cudaFuncAttributeMaxDynamicSharedMemorySize, ATT_SMEM);

    const float* wlist1[13] = {wq1,wk1,wv1,wg1,wo1,wq2,wk2,wv2,wg2,wo2,swg,sw1,sw2};
    ConvW cw{};
    for (int blk=0; blk<3; blk++)
        for (int j=0; j<13; j++){
            cw.src[blk*13+j] = wlist1[j] + (size_t)blk*EMB*EMB;
            cw.sz[blk*13+j] = EMB*EMB;
        }
    cw.src[39] = w_enc; cw.sz[39] = ADIM*EMB;
    cw.src[40] = hw1;   cw.sz[40] = EMB*EMB;
    cw.src[41] = hw2;   cw.sz[41] = EMB*ADIM;

    conv_w<<<dim3(NSLOT,32),256>>>(cw, wH, wL);
    conv_a<<<2048,256>>>(action, aH, aL, MROWS*ADIM);
    conv_a<<<4096,256>>>(obs, oH, oL, MROWS*EMB);

    auto WHs = [&](int slot){ return (const __nv_bfloat16*)(wH + (size_t)slot*SLOT_SZ); };
    auto WLs = [&](int slot){ return (const __nv_bfloat16*)(wL + (size_t)slot*SLOT_SZ); };

    auto mk1 = [&](const __nv_bfloat16* ah, const __nv_bfloat16* al, int slot,
                   float* c, const float* bias, const float* aux,
                   __nv_bfloat16* ch, __nv_bfloat16* cl, int N, int K){
        GemmP p{};
        for (int i=0;i<4;i++){ p.AH[i]=ah; p.AL[i]=al; p.WH[i]=WHs(slot); p.WL[i]=WLs(slot); p.C[i]=c; }
        p.bias=bias; p.aux=aux; p.CH=ch; p.CL=cl; p.N=N; p.K=K;
        return p;
    };

    const dim3 g1(MROWS/128, 4);
    const dim3 g4(MROWS/128, 16);
    const dim3 gHead(MROWS/128, 1);
    const dim3 gAttn(SEQ/128, NHEAD, BATCH);

    // encoder
    hgemm<1><<<g1,256,SMEM_TOT>>>(mk1(aH, aL, 39, tb, nullptr, nullptr, nullptr, nullptr, EMB, ADIM));
    rmsnorm_kernel<<<MROWS,256>>>(tb, nullptr, ln0, x, xH, xL);

    for (int blk=0; blk<3; blk++){
        const int s0 = blk*13;
        const size_t vOff = (size_t)blk*EMB;

        // retention 1: q/k/v/g projections with fused scale/split/swish epilogue
        {
            GemmP p{};
            const int slots[4] = {s0+0, s0+1, s0+2, s0+3};
            __nv_bfloat16* chs[4] = {qH, kH, vH, nullptr};
            __nv_bfloat16* cls[4] = {qL, kL, vL, nullptr};
            const int modes[4] = {1, 2, 3, 4};
            for (int i=0;i<4;i++){
                p.AH[i]=xH; p.AL[i]=xL;
                p.WH[i]=WHs(slots[i]); p.WL[i]=WLs(slots[i]);
                p.C[i]=gw; p.CH4[i]=chs[i]; p.CL4[i]=cls[i]; p.mode[i]=modes[i];
            }
            p.N=EMB; p.K=EMB;
            hgemm<5><<<g4,256,SMEM_TOT>>>(p);
        }
        attn_tc<<<gAttn,256,ATT_SMEM>>>(qH, qL, kH, kL, vH, vL, gw, gns1+vOff, gnb1+vOff, zH, zL);
        hgemm<0><<<g1,256,SMEM_TOT>>>(mk1(zH, zL, s0+4, tb, nullptr, nullptr, nullptr, nullptr, EMB, EMB));
        // ln1: fp32 output never read downstream -> skip it
        rmsnorm_kernel<<<MROWS,256>>>(x, tb, ln1+vOff, nullptr, xH, xL);

        // retention 2: q/g from obs, k/v from x
        {
            GemmP p{};
            const int slots[4] = {s0+5, s0+6, s0+7, s0+8};
            const __nv_bfloat16* ahs[4] = {oH, xH, xH, oH};
            const __nv_bfloat16* als[4] = {oL, xL, xL, oL};
            __nv_bfloat16* chs[4] = {qH, kH, vH, nullptr};
            __nv_bfloat16* cls[4] = {qL, kL, vL, nullptr};
            const int modes[4] = {1, 2, 3, 4};
            for (int i=0;i<4;i++){
                p.AH[i]=ahs[i]; p.AL[i]=als[i];
                p.WH[i]=WHs(slots[i]); p.WL[i]=WLs(slots[i]);
                p.C[i]=gw; p.CH4[i]=chs[i]; p.CL4[i]=cls[i]; p.mode[i]=modes[i];
            }
            p.N=EMB; p.K=EMB;
            hgemm<5><<<g4,256,SMEM_TOT>>>(p);
        }
        attn_tc<<<gAttn,256,ATT_SMEM>>>(qH, qL, kH, kL, vH, vL, gw, gns2+vOff, gnb2+vOff, zH, zL);
        hgemm<0><<<g1,256,SMEM_TOT>>>(mk1(zH, zL, s0+9, tb, nullptr, nullptr, nullptr, nullptr, EMB, EMB));
        rmsnorm_kernel<<<MROWS,256>>>(obs, tb, ln2+vOff, x, xH, xL);

        // swiglu
        hgemm<0><<<g1,256,SMEM_TOT>>>(mk1(xH, xL, s0+11, tb, nullptr, nullptr, nullptr, nullptr, EMB, EMB));
        hgemm<2><<<g1,256,SMEM_TOT>>>(mk1(xH, xL, s0+10, nullptr, nullptr, tb, zH, zL, EMB, EMB));
        hgemm<0><<<g1,256,SMEM_TOT>>>(mk1(zH, zL, s0+12, tb, nullptr, nullptr, nullptr, nullptr, EMB, EMB));
        rmsnorm_kernel<<<MROWS,256>>>(x, tb, ln3+vOff, x, xH, xL);
    }

    // head
    hgemm<1><<<g1,256,SMEM_TOT>>>(mk1(xH, xL, 40, tb, hb1, nullptr, nullptr, nullptr, EMB, EMB));
    rmsnorm_kernel<<<MROWS,256>>>(tb, nullptr, hln, zb, zH, zL);
    hgemm<3><<<gHead,256,SMEM_TOT>>>(mk1(zH, zL, 41, out, hb2, nullptr, nullptr, nullptr, ADIM, EMB));
}